// round 13
// baseline (speedup 1.0000x reference)
#include <cuda_runtime.h>
#include <cuda_fp16.h>
#include <cstdint>
#include <math.h>

// ===========================================================================
// CapsNet forward, B=512 — Round 13:
//  * conv1mma: M=256 x N=64, grid 3200, acc 32 regs, __launch_bounds__(512,2)
//    -> 2 CTAs/SM (register-limited occupancy fixed). B staging total
//    unchanged (N-split is free); A still one cp.async.bulk per chunk.
//  * k_uhat: uint4 stores (20 iters), same summation order.
//  * k_wprep: grid (256,2) over the cc halves.
//  * conv2 untouched (at tensor floor; M-split would double B-issue).
// ===========================================================================

// ------------------------------ scratch ------------------------------------
__device__ __align__(128) __half g_x2col[512u * 400u * 256u];  // 105 MB
__device__ __align__(128) __half g_w1t [4u * 16384u];          // 128 KB
__device__ __align__(128) __half g_h1t [512u * 400u * 256u];   // 105 MB NHWC
__device__ __align__(128) __half g_w2t [81u * 4u * 16384u];    // 10.6 MB
__device__ float  g_h2[512u * 9216u];
__device__ float  g_u [512u * 9216u];
__device__ __half g_uhat_h[512u * 1152u * 160u];               // 188.7 MB
__device__ float  g_spart[9u * 512u * 160u];
__device__ float  g_vsum[512u * 160u];

// ------------------------------ PTX helpers --------------------------------
__device__ __forceinline__ uint32_t smem_u32(const void* p) {
    uint32_t a;
    asm("{ .reg .u64 t; cvta.to.shared.u64 t, %1; cvt.u32.u64 %0, t; }"
        : "=r"(a) : "l"(p));
    return a;
}
#define CP16(dst, src) \
    asm volatile("cp.async.cg.shared.global [%0], [%1], 16;" :: "r"(dst), "l"(src) : "memory")
#define CP_COMMIT() asm volatile("cp.async.commit_group;" ::: "memory")
#define CP_WAIT1()  asm volatile("cp.async.wait_group 1;" ::: "memory")
#define CP_WAIT0()  asm volatile("cp.async.wait_group 0;" ::: "memory")

#define MBAR_INIT(a, n) \
    asm volatile("mbarrier.init.shared.b64 [%0], %1;" :: "r"(a), "r"(n) : "memory")
#define MBAR_EXPECT_TX(a, bytes) \
    asm volatile("mbarrier.arrive.expect_tx.shared.b64 _, [%0], %1;" \
                 :: "r"(a), "r"(bytes) : "memory")
#define MBAR_WAIT(a, ph) do {                                                  \
    uint32_t _m = (a), _p = (ph), _d;                                          \
    asm volatile("{ .reg .pred p;"                                             \
        "mbarrier.try_wait.parity.acquire.cta.shared::cta.b64 p, [%1], %2;"    \
        "selp.b32 %0,1,0,p; }" : "=r"(_d) : "r"(_m), "r"(_p) : "memory");      \
    if (!_d) {                                                                 \
        asm volatile("{ .reg .pred P1; WL_%=:"                                 \
            "mbarrier.try_wait.parity.acquire.cta.shared::cta.b64 P1, [%0], %1, 0x989680;" \
            "@P1 bra.uni WD_%=; bra.uni WL_%=; WD_%=: }"                       \
            :: "r"(_m), "r"(_p) : "memory");                                   \
    }                                                                          \
} while (0)
#define BULK_G2S(dst, src, size, mbar) \
    asm volatile("cp.async.bulk.shared::cta.global.mbarrier::complete_tx::bytes " \
                 "[%0], [%1], %2, [%3];" \
                 :: "r"(dst), "l"(src), "r"(size), "r"(mbar) : "memory")

__device__ __forceinline__ void ldsm_x4(uint32_t* r, uint32_t addr) {
    asm volatile("ldmatrix.sync.aligned.m8n8.x4.shared.b16 {%0,%1,%2,%3}, [%4];"
                 : "=r"(r[0]), "=r"(r[1]), "=r"(r[2]), "=r"(r[3]) : "r"(addr));
}
__device__ __forceinline__ void mma16816h(float* c, const uint32_t* a,
                                          const uint32_t* b) {
    asm volatile("mma.sync.aligned.m16n8k16.row.col.f32.f16.f16.f32 "
                 "{%0,%1,%2,%3}, {%4,%5,%6,%7}, {%8,%9}, {%0,%1,%2,%3};"
                 : "+f"(c[0]), "+f"(c[1]), "+f"(c[2]), "+f"(c[3])
                 : "r"(a[0]), "r"(a[1]), "r"(a[2]), "r"(a[3]),
                   "r"(b[0]), "r"(b[1]));
}
__device__ __forceinline__ uint32_t swz(uint32_t o) {
    return o ^ ((o >> 3) & 0x70);
}

// ---------------------------------------------------------------------------
// im2col (unchanged R12)
// ---------------------------------------------------------------------------
__global__ __launch_bounds__(256) void k_im2col(const float* __restrict__ x)
{
    __shared__ float xs[2352];
    const int b    = blockIdx.x;
    const int tid  = threadIdx.x;
    const int warp = tid >> 5;
    const int lane = tid & 31;
    {
        const float4* xg = (const float4*)(x + b * 2352);
        float4* xs4 = (float4*)xs;
        for (int i = tid; i < 588; i += 256) xs4[i] = xg[i];
    }
    int l[8];
#pragma unroll
    for (int j = 0; j < 8; j++) {
        const int k = lane * 8 + j;
        if (k < 243) {
            const int c = k / 81, kk = k - c * 81;
            const int ky = kk / 9, kx = kk - ky * 9;
            l[j] = c * 784 + ky * 28 + kx;
        } else l[j] = -1;
    }
    __syncthreads();

    for (int p = warp; p < 400; p += 8) {
        const int oy = p / 20, ox = p - (p / 20) * 20;
        const int off = oy * 28 + ox;
        __align__(16) __half vals[8];
#pragma unroll
        for (int j = 0; j < 8; j++)
            vals[j] = (l[j] >= 0) ? __float2half(xs[l[j] + off]) : __half(0.f);
        *(uint4*)&g_x2col[((size_t)b * 400 + p) * 256 + lane * 8] =
            *(const uint4*)vals;
    }
}

// ---------------------------------------------------------------------------
// w1 prep (unchanged R12)
// ---------------------------------------------------------------------------
__global__ __launch_bounds__(256) void k_w1prep(const float* __restrict__ w1)
{
    const int co = blockIdx.x;
    const int k  = threadIdx.x;
    float v = (k < 243) ? w1[co * 243 + k] : 0.f;
    const int cq  = k >> 6;
    const int k64 = k & 63;
    const uint32_t inner = swz((uint32_t)co * 128 + k64 * 2) >> 1;
    g_w1t[cq * 16384 + inner] = __float2half(v);
}

// ---------------------------------------------------------------------------
// conv1 GEMM: M=256 co x N=64 pos. grid 3200, block 512, 2 CTA/SM.
// Stage 40KB: A[32K]|B[8K]; 2 stages (81920); mbar @81920. 4 K64 chunks.
// Warps 4(M:64co) x 4(N:16pos); mf 0..3, nf 0..1; acc 32 regs.
// ---------------------------------------------------------------------------
#define C1_STAGE 40960
#define C1_B_OFF 32768
#define C1_MB    81920
#define C1_NCH   4

__global__ __launch_bounds__(512, 2) void k_conv1mma(const float* __restrict__ b1)
{
    extern __shared__ __align__(1024) char dynsmem[];
    const uint32_t sb = smem_u32(dynsmem);
    const int tid  = threadIdx.x;
    const int warp = tid >> 5;
    const int lane = tid & 31;
    const int n0    = blockIdx.x * 64;
    const int mwarp = warp & 3;       // co: mwarp*64
    const int nwarp = warp >> 2;      // n : nwarp*16

    if (tid == 0) {
        MBAR_INIT(sb + C1_MB, 1);
        MBAR_INIT(sb + C1_MB + 8, 1);
    }
    __syncthreads();

    // B loader: one CP16 per thread (64 rows x 8)
    const int uB   = tid & 7;
    const int row0 = tid >> 3;        // 0..63
    const uint32_t pixBase = (uint32_t)(n0 + row0) * 256u + uB * 8;
    const uint32_t bDst    = swz((uint32_t)row0 * 128 + uB * 16);

    const int aRowSub = lane & 15;
    const int aColSel = (lane >> 4) * 16;
    const int bMat    = lane >> 3;
    const int bSub    = lane & 7;
    const int bNfSel  = bMat >> 1;
    const int bKSel   = (bMat & 1) * 16;

    float acc[4][2][4];
#pragma unroll
    for (int mf = 0; mf < 4; mf++)
#pragma unroll
        for (int nf = 0; nf < 2; nf++)
#pragma unroll
            for (int i = 0; i < 4; i++) acc[mf][nf][i] = 0.f;

    if (tid == 0) {
        MBAR_EXPECT_TX(sb + C1_MB, 32768);
        BULK_G2S(sb, (const char*)g_w1t, 32768, sb + C1_MB);
    }
    CP16(sb + C1_B_OFF + bDst, g_x2col + pixBase);
    CP_COMMIT();

    for (int t = 0; t < C1_NCH; t++) {
        const int s = t & 1, s2 = s ^ 1;
        if (t + 1 < C1_NCH) {
            const int tn = t + 1;
            if (tid == 0) {
                MBAR_EXPECT_TX(sb + C1_MB + 8 * s2, 32768);
                BULK_G2S(sb + s2 * C1_STAGE,
                         (const char*)(g_w1t + (size_t)tn * 16384),
                         32768, sb + C1_MB + 8 * s2);
            }
            CP16(sb + s2 * C1_STAGE + C1_B_OFF + bDst,
                 g_x2col + pixBase + tn * 64);
            CP_COMMIT();
            CP_WAIT1();
        } else {
            CP_WAIT0();
        }
        MBAR_WAIT(sb + C1_MB + 8 * s, (t >> 1) & 1);
        __syncthreads();

        const uint32_t stb = sb + s * C1_STAGE;
        const uint32_t aa = stb;
        const uint32_t bb = stb + C1_B_OFF;

#pragma unroll
        for (int q = 0; q < 4; q++) {
            const int qb = q * 32;
            uint32_t B[2][2];
            {
                uint32_t off = swz((nwarp * 16 + bNfSel * 8 + bSub) * 128
                                   + qb + bKSel);
                uint32_t r[4];
                ldsm_x4(r, bb + off);
                B[0][0] = r[0]; B[0][1] = r[1];
                B[1][0] = r[2]; B[1][1] = r[3];
            }
#pragma unroll
            for (int mf = 0; mf < 4; mf++) {
                uint32_t A[4];
                uint32_t offA = swz((mwarp * 64 + mf * 16 + aRowSub) * 128
                                    + qb + aColSel);
                ldsm_x4(A, aa + offA);
#pragma unroll
                for (int nf = 0; nf < 2; nf++)
                    mma16816h(acc[mf][nf], A, B[nf]);
            }
        }
        __syncthreads();
    }

    // epilogue: bias + relu + fp16 via smem transpose -> coalesced h1t rows
    __half* ebuf = (__half*)dynsmem;        // 64 x 256 halfs = 32KB
#pragma unroll
    for (int mf = 0; mf < 4; mf++) {
        const int coB = mwarp * 64 + mf * 16 + (lane >> 2);
        const float bias0 = b1[coB];
        const float bias1 = b1[coB + 8];
#pragma unroll
        for (int nf = 0; nf < 2; nf++) {
#pragma unroll
            for (int i = 0; i < 4; i++) {
                const int co = coB + ((i >> 1) << 3);
                const int nl = nwarp * 16 + nf * 8 + ((lane & 3) << 1) + (i & 1);
                const float v = acc[mf][nf][i] + ((i >> 1) ? bias1 : bias0);
                ebuf[nl * 256 + co] = __float2half(fmaxf(v, 0.f));
            }
        }
    }
    __syncthreads();
    for (int f = tid; f < 64 * 32; f += 512) {
        const int rw = f >> 5;
        const int j  = f & 31;
        *(uint4*)&g_h1t[(size_t)(n0 + rw) * 256 + j * 8] =
            *(const uint4*)&ebuf[rw * 256 + j * 8];
    }
}

// ---------------------------------------------------------------------------
// W2 prep, cc split across blockIdx.y. grid (256, 2), block 256.
// ---------------------------------------------------------------------------
__global__ __launch_bounds__(256) void k_wprep(const float* __restrict__ w2)
{
    __shared__ float wt[128 * 81];
    const int co  = blockIdx.x;
    const int cc  = blockIdx.y;
    const int id  = threadIdx.x;
    const int c   = id & 127;
    const int hf  = id >> 7;

    const float* src = w2 + (size_t)co * 20736 + cc * 128 * 81;
    for (int i = id; i < 128 * 81; i += 256) wt[i] = src[i];
    __syncthreads();
    const int cglob = cc * 128 + c;
    const int cq    = cglob >> 6;
    const int c64   = cglob & 63;
    const uint32_t inner = swz((uint32_t)co * 128 + c64 * 2) >> 1;
    const int k0 = hf ? 41 : 0;
    const int k1 = hf ? 81 : 41;
    for (int kk = k0; kk < k1; kk++) {
        g_w2t[(size_t)(kk * 4 + cq) * 16384 + inner] =
            __float2half(wt[c * 81 + kk]);
    }
}

// ---------------------------------------------------------------------------
// conv2 implicit GEMM (unchanged R10/R12). grid 144, block 512.
// ---------------------------------------------------------------------------
#define STAGE_BYTES 49152
#define A_BYTES 32768
#define B_OFF 32768
#define MB_OFF 98304
#define NCHUNK 324

__global__ __launch_bounds__(512) void k_conv2mma(const float* __restrict__ b2)
{
    extern __shared__ __align__(1024) char dynsmem[];
    const uint32_t sb = smem_u32(dynsmem);
    const int tid  = threadIdx.x;
    const int warp = tid >> 5;
    const int lane = tid & 31;
    const int n0    = blockIdx.x * 128;
    const int mwarp = warp & 3;
    const int nwarp = warp >> 2;

    if (tid == 0) {
        MBAR_INIT(sb + MB_OFF, 1);
        MBAR_INIT(sb + MB_OFF + 8, 1);
    }
    __syncthreads();

    const int uB = tid & 7;
    int pixBase[2];
#pragma unroll
    for (int h = 0; h < 2; h++) {
        const int n    = n0 + (tid >> 3) + h * 64;
        const int bimg = n / 36;
        const int pos  = n - bimg * 36;
        const int oy   = pos / 6, ox = pos - oy * 6;
        pixBase[h] = (bimg * 400 + oy * 40 + ox * 2) * 256 + uB * 8;
    }
    uint32_t bDst[2];
    bDst[0] = swz((uint32_t)(tid >> 3) * 128 + uB * 16);
    bDst[1] = swz(((uint32_t)(tid >> 3) + 64) * 128 + uB * 16);

    const int aRowSub = lane & 15;
    const int aColSel = (lane >> 4) * 16;
    const int bMat    = lane >> 3;
    const int bSub    = lane & 7;
    const int bNfSel  = bMat >> 1;
    const int bKSel   = (bMat & 1) * 16;

    float acc[4][4][4];
#pragma unroll
    for (int mf = 0; mf < 4; mf++)
#pragma unroll
        for (int nf = 0; nf < 4; nf++)
#pragma unroll
            for (int i = 0; i < 4; i++) acc[mf][nf][i] = 0.f;

    if (tid == 0) {
        MBAR_EXPECT_TX(sb + MB_OFF, A_BYTES);
        BULK_G2S(sb, (const char*)g_w2t, A_BYTES, sb + MB_OFF);
    }
#pragma unroll
    for (int h = 0; h < 2; h++)
        CP16(sb + B_OFF + bDst[h], g_h1t + pixBase[h]);
    CP_COMMIT();

    for (int t = 0; t < NCHUNK; t++) {
        const int s = t & 1, s2 = s ^ 1;
        if (t + 1 < NCHUNK) {
            const int tn = t + 1;
            const int kk = tn >> 2, cq = tn & 3;
            if (tid == 0) {
                MBAR_EXPECT_TX(sb + MB_OFF + 8 * s2, A_BYTES);
                BULK_G2S(sb + s2 * STAGE_BYTES,
                         (const char*)(g_w2t + (size_t)tn * 16384),
                         A_BYTES, sb + MB_OFF + 8 * s2);
            }
            const int ky = kk / 9, kx = kk - ky * 9;
            const int tap  = (ky * 20 + kx) * 256;
            const int cOff = cq * 64;
#pragma unroll
            for (int h = 0; h < 2; h++)
                CP16(sb + s2 * STAGE_BYTES + B_OFF + bDst[h],
                     g_h1t + pixBase[h] + tap + cOff);
            CP_COMMIT();
            CP_WAIT1();
        } else {
            CP_WAIT0();
        }
        MBAR_WAIT(sb + MB_OFF + 8 * s, (t >> 1) & 1);
        __syncthreads();

        const uint32_t stb = sb + s * STAGE_BYTES;
        const uint32_t aa = stb;
        const uint32_t bb = stb + B_OFF;

#pragma unroll
        for (int q = 0; q < 4; q++) {
            const int qb = q * 32;
            uint32_t B[4][2];
#pragma unroll
            for (int gp = 0; gp < 2; gp++) {
                uint32_t off = swz((nwarp * 32 + (gp * 2 + bNfSel) * 8 + bSub) * 128
                                   + qb + bKSel);
                uint32_t r[4];
                ldsm_x4(r, bb + off);
                B[gp*2][0] = r[0]; B[gp*2][1] = r[1];
                B[gp*2+1][0] = r[2]; B[gp*2+1][1] = r[3];
            }
#pragma unroll
            for (int mf = 0; mf < 4; mf++) {
                uint32_t A[4];
                uint32_t offA = swz((mwarp * 64 + mf * 16 + aRowSub) * 128
                                    + qb + aColSel);
                ldsm_x4(A, aa + offA);
#pragma unroll
                for (int nf = 0; nf < 4; nf++)
                    mma16816h(acc[mf][nf], A, B[nf]);
            }
        }
        __syncthreads();
    }

#pragma unroll
    for (int mf = 0; mf < 4; mf++) {
        const int coB = mwarp * 64 + mf * 16 + (lane >> 2);
        const float bias0 = b2[coB];
        const float bias1 = b2[coB + 8];
#pragma unroll
        for (int nf = 0; nf < 4; nf++) {
#pragma unroll
            for (int i = 0; i < 4; i++) {
                const int co = coB + ((i >> 1) << 3);
                const int n  = n0 + nwarp * 32 + nf * 8 + ((lane & 3) << 1) + (i & 1);
                const int bi = n / 36;
                const int pp = n - bi * 36;
                g_h2[(size_t)bi * 9216 + co * 36 + pp] =
                    acc[mf][nf][i] + ((i >> 1) ? bias1 : bias0);
            }
        }
    }
}

// ---------------------------------------------------------------------------
// primary capsule squash (unchanged)
// ---------------------------------------------------------------------------
__global__ __launch_bounds__(256) void k_squash_pc()
{
    unsigned idx = blockIdx.x * 256u + threadIdx.x;
    if (idx >= 589824u) return;
    const float4* p = (const float4*)(g_h2 + (size_t)idx * 8);
    float4 a = p[0], b = p[1];
    float sn = a.x*a.x + a.y*a.y + a.z*a.z + a.w*a.w
             + b.x*b.x + b.y*b.y + b.z*b.z + b.w*b.w;
    float sc = sn / ((1.f + sn) * (sqrtf(sn) + 1e-6f));
    a.x *= sc; a.y *= sc; a.z *= sc; a.w *= sc;
    b.x *= sc; b.y *= sc; b.z *= sc; b.w *= sc;
    float4* q = (float4*)(g_u + (size_t)idx * 8);
    q[0] = a; q[1] = b;
}

// ---------------------------------------------------------------------------
// u_hat -> fp16, uint4 stores (8 e per thread per iter). grid (288,4), blk 256.
// ---------------------------------------------------------------------------
__global__ __launch_bounds__(256) void k_uhat(const float* __restrict__ W, int b0)
{
    __shared__ float Wsm[4 * 1280];
    __shared__ float usm[64 * 32];
    const int capg = blockIdx.x * 4;
    const int img0 = b0 + blockIdx.y * 64;
    const int id   = threadIdx.x;
    {
        const float4* Wg = (const float4*)(W + (size_t)capg * 1280);
        float4* Ws4 = (float4*)Wsm;
        for (int i = id; i < 1280; i += 256) Ws4[i] = Wg[i];
        float4* us4 = (float4*)usm;
        for (int i = id; i < 512; i += 256) {
            int im = i >> 3, r = i & 7;
            us4[i] = *(const float4*)(g_u + (size_t)(img0 + im) * 9216
                                      + capg * 8 + r * 4);
        }
    }
    __syncthreads();
    for (int it = 0; it < 20; it++) {
        int flat = it * 256 + id;       // < 64*4*20 = 5120
        int oe8  = flat % 20;
        int cap  = (flat / 20) & 3;
        int im   = flat / 80;
        int o    = oe8 >> 1;
        int e0   = (oe8 & 1) * 8;
        const float*  up = &usm[im * 32 + cap * 8];
        const float4* Wp = (const float4*)&Wsm[cap * 1280 + o * 128 + e0];
        float4 a0 = make_float4(0.f, 0.f, 0.f, 0.f);
        float4 a1 = make_float4(0.f, 0.f, 0.f, 0.f);
#pragma unroll
        for (int d = 0; d < 8; d++) {
            float  ud = up[d];
            float4 wa = Wp[d * 4];
            float4 wb = Wp[d * 4 + 1];
            a0.x = fmaf(ud, wa.x, a0.x); a0.y = fmaf(ud, wa.y, a0.y);
            a0.z = fmaf(ud, wa.z, a0.z); a0.w = fmaf(ud, wa.w, a0.w);
            a1.x = fmaf(ud, wb.x, a1.x); a1.y = fmaf(ud, wb.y, a1.y);
            a1.z = fmaf(ud, wb.z, a1.z); a1.w = fmaf(ud, wb.w, a1.w);
        }
        __half2 h0 = __floats2half2_rn(a0.x, a0.y);
        __half2 h1 = __floats2half2_rn(a0.z, a0.w);
        __half2 h2 = __floats2half2_rn(a1.x, a1.y);
        __half2 h3 = __floats2half2_rn(a1.z, a1.w);
        uint4 pk = make_uint4(*(uint32_t*)&h0, *(uint32_t*)&h1,
                              *(uint32_t*)&h2, *(uint32_t*)&h3);
        *(uint4*)&g_uhat_h[((size_t)(img0 + im) * 1152 + capg + cap) * 160
                           + o * 16 + e0] = pk;
    }
}

// ---------------------------------------------------------------------------
// fused routing iteration, b-chunked (unchanged R12)
// ---------------------------------------------------------------------------
__global__ __launch_bounds__(160) void k_route(int uniform, int b0)
{
    __shared__ __align__(16) __half tile[128 * 168];
    __shared__ float vs[160];
    __shared__ float c_sm[128][10];
    const int b     = b0 + blockIdx.x;
    const int chunk = blockIdx.y;
    const int tid   = threadIdx.x;
    const __half* ub = g_uhat_h + (size_t)b * 184320 + (size_t)chunk * 128 * 160;

    if (uniform) {
        const int oe = tid;
        float acc = 0.f;
#pragma unroll 4
        for (int cap = 0; cap < 128; cap++)
            acc += __half2float(ub[(size_t)cap * 160 + oe]);
        g_spart[((size_t)chunk * 512 + b) * 160 + oe] = acc * 0.1f;
        return;
    }

    vs[tid] = g_vsum[b * 160 + tid];
    for (int f = tid; f < 2560; f += 160) {
        const int r = f / 20, j = f % 20;
        *(uint4*)&tile[r * 168 + j * 8] = *(const uint4*)(ub + (size_t)r * 160 + j * 8);
    }
    __syncthreads();

    if (tid < 128) {
        const __half2* row = (const __half2*)&tile[tid * 168];
        float t[10];
#pragma unroll
        for (int o = 0; o < 10; o++) {
            float s = 0.f;
#pragma unroll
            for (int e2 = 0; e2 < 8; e2++) {
                float2 f = __half22float2(row[o * 8 + e2]);
                s += f.x * vs[o * 16 + e2 * 2] + f.y * vs[o * 16 + e2 * 2 + 1];
            }
            t[o] = s;
        }
        float m = t[0];
#pragma unroll
        for (int o = 1; o < 10; o++) m = fmaxf(m, t[o]);
        float se = 0.f;
#pragma unroll
        for (int o = 0; o < 10; o++) { t[o] = expf(t[o] - m); se += t[o]; }
        float inv = 1.f / se;
#pragma unroll
        for (int o = 0; o < 10; o++) c_sm[tid][o] = t[o] * inv;
    }
    __syncthreads();

    const int oe = tid;
    const int o  = oe >> 4;
    float acc = 0.f;
#pragma unroll 4
    for (int cap = 0; cap < 128; cap++)
        acc = fmaf(c_sm[cap][o], __half2float(tile[cap * 168 + oe]), acc);
    g_spart[((size_t)chunk * 512 + b) * 160 + oe] = acc;
}

// ---------------------------------------------------------------------------
// sum partials + squash, b-chunked (unchanged R12)
// ---------------------------------------------------------------------------
__global__ void k_squash_v(float* __restrict__ out, int mode, int b0)
{
    int lidx = blockIdx.x * 256 + threadIdx.x;
    if (lidx >= 2560) return;
    const size_t idx = (size_t)b0 * 10 + lidx;
    float4 r[4];
#pragma unroll
    for (int i = 0; i < 4; i++) r[i] = make_float4(0.f, 0.f, 0.f, 0.f);
#pragma unroll
    for (int p = 0; p < 9; p++) {
        const float4* sp = (const float4*)(g_spart + (size_t)p * 81920
                                           + idx * 16);
#pragma unroll
        for (int i = 0; i < 4; i++) {
            float4 v = sp[i];
            r[i].x += v.x; r[i].y += v.y; r[i].z += v.z; r[i].w += v.w;
        }
    }
    float sn = 0.f;
#pragma unroll
    for (int i = 0; i < 4; i++)
        sn += r[i].x*r[i].x + r[i].y*r[i].y + r[i].z*r[i].z + r[i].w*r[i].w;
    float sc = sn / ((1.f + sn) * (sqrtf(sn) + 1e-6f));
#pragma unroll
    for (int i = 0; i < 4; i++) {
        r[i].x *= sc; r[i].y *= sc; r[i].z *= sc; r[i].w *= sc;
    }
    if (mode == 0) {
        float4* q = (float4*)(g_vsum + idx * 16);
#pragma unroll
        for (int i = 0; i < 4; i++) q[i] = r[i];
    } else if (mode == 1) {
        float4* q = (float4*)(g_vsum + idx * 16);
#pragma unroll
        for (int i = 0; i < 4; i++) {
            float4 old = q[i];
            old.x += r[i].x; old.y += r[i].y; old.z += r[i].z; old.w += r[i].w;
            q[i] = old;
        }
    } else {
        float4* q = (float4*)(out + idx * 16);
#pragma unroll
        for (int i = 0; i < 4; i++) q[i] = r[i];
    }
}

// ---------------------------------------------------------------------------
extern "C" void kernel_launch(void* const* d_in, const int* in_sizes, int n_in,
                              void* d_out, int out_size)
{
    const float* x   = (const float*)d_in[0];
    const float* w1  = (const float*)d_in[1];
    const float* b1  = (const float*)d_in[2];
    const float* w2  = (const float*)d_in[3];
    const float* b2  = (const float*)d_in[4];
    const float* W   = (const float*)d_in[5];
    float* out = (float*)d_out;

    cudaFuncSetAttribute(k_conv1mma,
                         cudaFuncAttributeMaxDynamicSharedMemorySize, 81952);
    cudaFuncSetAttribute(k_conv2mma,
                         cudaFuncAttributeMaxDynamicSharedMemorySize, 98336);

    k_im2col<<<512, 256>>>(x);
    k_w1prep<<<256, 256>>>(w1);
    k_wprep<<<dim3(256, 2), 256>>>(w2);
    k_conv1mma<<<3200, 512, 81952>>>(b1);
    k_conv2mma<<<144, 512, 98336>>>(b2);
    k_squash_pc<<<2304, 256>>>();

    for (int c = 0; c < 2; c++) {
        const int b0 = c * 256;
        k_uhat<<<dim3(288, 4), 256>>>(W, b0);
        k_route<<<dim3(256, 9), 160>>>(1, b0);
        k_squash_v<<<10, 256>>>(nullptr, 0, b0);
        k_route<<<dim3(256, 9), 160>>>(0, b0);
        k_squash_v<<<10, 256>>>(nullptr, 1, b0);
        k_route<<<dim3(256, 9), 160>>>(0, b0);
        k_squash_v<<<10, 256>>>(out, 2, b0);
    }
}

// round 14
// speedup vs baseline: 1.1148x; 1.1148x over previous
#include <cuda_runtime.h>
#include <cuda_fp16.h>
#include <cstdint>
#include <math.h>

// ===========================================================================
// CapsNet forward, B=512 — Round 14:
//  * revert k_uhat to R12 40-iter form (R13 uint4 rewrite caused the +143us)
//  * keep conv1mma M=256xN=64 (measured 110.6us, 2 CTA/SM)
//  * fuse primary-capsule squash INTO k_uhat (reads g_h2 directly; g_u and
//    k_squash_pc deleted)
// ===========================================================================

// ------------------------------ scratch ------------------------------------
__device__ __align__(128) __half g_x2col[512u * 400u * 256u];  // 105 MB
__device__ __align__(128) __half g_w1t [4u * 16384u];          // 128 KB
__device__ __align__(128) __half g_h1t [512u * 400u * 256u];   // 105 MB NHWC
__device__ __align__(128) __half g_w2t [81u * 4u * 16384u];    // 10.6 MB
__device__ float  g_h2[512u * 9216u];
__device__ __half g_uhat_h[512u * 1152u * 160u];               // 188.7 MB
__device__ float  g_spart[9u * 512u * 160u];
__device__ float  g_vsum[512u * 160u];

// ------------------------------ PTX helpers --------------------------------
__device__ __forceinline__ uint32_t smem_u32(const void* p) {
    uint32_t a;
    asm("{ .reg .u64 t; cvta.to.shared.u64 t, %1; cvt.u32.u64 %0, t; }"
        : "=r"(a) : "l"(p));
    return a;
}
#define CP16(dst, src) \
    asm volatile("cp.async.cg.shared.global [%0], [%1], 16;" :: "r"(dst), "l"(src) : "memory")
#define CP_COMMIT() asm volatile("cp.async.commit_group;" ::: "memory")
#define CP_WAIT1()  asm volatile("cp.async.wait_group 1;" ::: "memory")
#define CP_WAIT0()  asm volatile("cp.async.wait_group 0;" ::: "memory")

#define MBAR_INIT(a, n) \
    asm volatile("mbarrier.init.shared.b64 [%0], %1;" :: "r"(a), "r"(n) : "memory")
#define MBAR_EXPECT_TX(a, bytes) \
    asm volatile("mbarrier.arrive.expect_tx.shared.b64 _, [%0], %1;" \
                 :: "r"(a), "r"(bytes) : "memory")
#define MBAR_WAIT(a, ph) do {                                                  \
    uint32_t _m = (a), _p = (ph), _d;                                          \
    asm volatile("{ .reg .pred p;"                                             \
        "mbarrier.try_wait.parity.acquire.cta.shared::cta.b64 p, [%1], %2;"    \
        "selp.b32 %0,1,0,p; }" : "=r"(_d) : "r"(_m), "r"(_p) : "memory");      \
    if (!_d) {                                                                 \
        asm volatile("{ .reg .pred P1; WL_%=:"                                 \
            "mbarrier.try_wait.parity.acquire.cta.shared::cta.b64 P1, [%0], %1, 0x989680;" \
            "@P1 bra.uni WD_%=; bra.uni WL_%=; WD_%=: }"                       \
            :: "r"(_m), "r"(_p) : "memory");                                   \
    }                                                                          \
} while (0)
#define BULK_G2S(dst, src, size, mbar) \
    asm volatile("cp.async.bulk.shared::cta.global.mbarrier::complete_tx::bytes " \
                 "[%0], [%1], %2, [%3];" \
                 :: "r"(dst), "l"(src), "r"(size), "r"(mbar) : "memory")

__device__ __forceinline__ void ldsm_x4(uint32_t* r, uint32_t addr) {
    asm volatile("ldmatrix.sync.aligned.m8n8.x4.shared.b16 {%0,%1,%2,%3}, [%4];"
                 : "=r"(r[0]), "=r"(r[1]), "=r"(r[2]), "=r"(r[3]) : "r"(addr));
}
__device__ __forceinline__ void mma16816h(float* c, const uint32_t* a,
                                          const uint32_t* b) {
    asm volatile("mma.sync.aligned.m16n8k16.row.col.f32.f16.f16.f32 "
                 "{%0,%1,%2,%3}, {%4,%5,%6,%7}, {%8,%9}, {%0,%1,%2,%3};"
                 : "+f"(c[0]), "+f"(c[1]), "+f"(c[2]), "+f"(c[3])
                 : "r"(a[0]), "r"(a[1]), "r"(a[2]), "r"(a[3]),
                   "r"(b[0]), "r"(b[1]));
}
__device__ __forceinline__ uint32_t swz(uint32_t o) {
    return o ^ ((o >> 3) & 0x70);
}

// ---------------------------------------------------------------------------
// im2col (unchanged R12)
// ---------------------------------------------------------------------------
__global__ __launch_bounds__(256) void k_im2col(const float* __restrict__ x)
{
    __shared__ float xs[2352];
    const int b    = blockIdx.x;
    const int tid  = threadIdx.x;
    const int warp = tid >> 5;
    const int lane = tid & 31;
    {
        const float4* xg = (const float4*)(x + b * 2352);
        float4* xs4 = (float4*)xs;
        for (int i = tid; i < 588; i += 256) xs4[i] = xg[i];
    }
    int l[8];
#pragma unroll
    for (int j = 0; j < 8; j++) {
        const int k = lane * 8 + j;
        if (k < 243) {
            const int c = k / 81, kk = k - c * 81;
            const int ky = kk / 9, kx = kk - ky * 9;
            l[j] = c * 784 + ky * 28 + kx;
        } else l[j] = -1;
    }
    __syncthreads();

    for (int p = warp; p < 400; p += 8) {
        const int oy = p / 20, ox = p - (p / 20) * 20;
        const int off = oy * 28 + ox;
        __align__(16) __half vals[8];
#pragma unroll
        for (int j = 0; j < 8; j++)
            vals[j] = (l[j] >= 0) ? __float2half(xs[l[j] + off]) : __half(0.f);
        *(uint4*)&g_x2col[((size_t)b * 400 + p) * 256 + lane * 8] =
            *(const uint4*)vals;
    }
}

// ---------------------------------------------------------------------------
// w1 prep (unchanged R12)
// ---------------------------------------------------------------------------
__global__ __launch_bounds__(256) void k_w1prep(const float* __restrict__ w1)
{
    const int co = blockIdx.x;
    const int k  = threadIdx.x;
    float v = (k < 243) ? w1[co * 243 + k] : 0.f;
    const int cq  = k >> 6;
    const int k64 = k & 63;
    const uint32_t inner = swz((uint32_t)co * 128 + k64 * 2) >> 1;
    g_w1t[cq * 16384 + inner] = __float2half(v);
}

// ---------------------------------------------------------------------------
// conv1 GEMM: M=256 co x N=64 pos. grid 3200, block 512, 2 CTA/SM (R13).
// ---------------------------------------------------------------------------
#define C1_STAGE 40960
#define C1_B_OFF 32768
#define C1_MB    81920
#define C1_NCH   4

__global__ __launch_bounds__(512, 2) void k_conv1mma(const float* __restrict__ b1)
{
    extern __shared__ __align__(1024) char dynsmem[];
    const uint32_t sb = smem_u32(dynsmem);
    const int tid  = threadIdx.x;
    const int warp = tid >> 5;
    const int lane = tid & 31;
    const int n0    = blockIdx.x * 64;
    const int mwarp = warp & 3;
    const int nwarp = warp >> 2;

    if (tid == 0) {
        MBAR_INIT(sb + C1_MB, 1);
        MBAR_INIT(sb + C1_MB + 8, 1);
    }
    __syncthreads();

    const int uB   = tid & 7;
    const int row0 = tid >> 3;
    const uint32_t pixBase = (uint32_t)(n0 + row0) * 256u + uB * 8;
    const uint32_t bDst    = swz((uint32_t)row0 * 128 + uB * 16);

    const int aRowSub = lane & 15;
    const int aColSel = (lane >> 4) * 16;
    const int bMat    = lane >> 3;
    const int bSub    = lane & 7;
    const int bNfSel  = bMat >> 1;
    const int bKSel   = (bMat & 1) * 16;

    float acc[4][2][4];
#pragma unroll
    for (int mf = 0; mf < 4; mf++)
#pragma unroll
        for (int nf = 0; nf < 2; nf++)
#pragma unroll
            for (int i = 0; i < 4; i++) acc[mf][nf][i] = 0.f;

    if (tid == 0) {
        MBAR_EXPECT_TX(sb + C1_MB, 32768);
        BULK_G2S(sb, (const char*)g_w1t, 32768, sb + C1_MB);
    }
    CP16(sb + C1_B_OFF + bDst, g_x2col + pixBase);
    CP_COMMIT();

    for (int t = 0; t < C1_NCH; t++) {
        const int s = t & 1, s2 = s ^ 1;
        if (t + 1 < C1_NCH) {
            const int tn = t + 1;
            if (tid == 0) {
                MBAR_EXPECT_TX(sb + C1_MB + 8 * s2, 32768);
                BULK_G2S(sb + s2 * C1_STAGE,
                         (const char*)(g_w1t + (size_t)tn * 16384),
                         32768, sb + C1_MB + 8 * s2);
            }
            CP16(sb + s2 * C1_STAGE + C1_B_OFF + bDst,
                 g_x2col + pixBase + tn * 64);
            CP_COMMIT();
            CP_WAIT1();
        } else {
            CP_WAIT0();
        }
        MBAR_WAIT(sb + C1_MB + 8 * s, (t >> 1) & 1);
        __syncthreads();

        const uint32_t stb = sb + s * C1_STAGE;
        const uint32_t aa = stb;
        const uint32_t bb = stb + C1_B_OFF;

#pragma unroll
        for (int q = 0; q < 4; q++) {
            const int qb = q * 32;
            uint32_t B[2][2];
            {
                uint32_t off = swz((nwarp * 16 + bNfSel * 8 + bSub) * 128
                                   + qb + bKSel);
                uint32_t r[4];
                ldsm_x4(r, bb + off);
                B[0][0] = r[0]; B[0][1] = r[1];
                B[1][0] = r[2]; B[1][1] = r[3];
            }
#pragma unroll
            for (int mf = 0; mf < 4; mf++) {
                uint32_t A[4];
                uint32_t offA = swz((mwarp * 64 + mf * 16 + aRowSub) * 128
                                    + qb + aColSel);
                ldsm_x4(A, aa + offA);
#pragma unroll
                for (int nf = 0; nf < 2; nf++)
                    mma16816h(acc[mf][nf], A, B[nf]);
            }
        }
        __syncthreads();
    }

    __half* ebuf = (__half*)dynsmem;
#pragma unroll
    for (int mf = 0; mf < 4; mf++) {
        const int coB = mwarp * 64 + mf * 16 + (lane >> 2);
        const float bias0 = b1[coB];
        const float bias1 = b1[coB + 8];
#pragma unroll
        for (int nf = 0; nf < 2; nf++) {
#pragma unroll
            for (int i = 0; i < 4; i++) {
                const int co = coB + ((i >> 1) << 3);
                const int nl = nwarp * 16 + nf * 8 + ((lane & 3) << 1) + (i & 1);
                const float v = acc[mf][nf][i] + ((i >> 1) ? bias1 : bias0);
                ebuf[nl * 256 + co] = __float2half(fmaxf(v, 0.f));
            }
        }
    }
    __syncthreads();
    for (int f = tid; f < 64 * 32; f += 512) {
        const int rw = f >> 5;
        const int j  = f & 31;
        *(uint4*)&g_h1t[(size_t)(n0 + rw) * 256 + j * 8] =
            *(const uint4*)&ebuf[rw * 256 + j * 8];
    }
}

// ---------------------------------------------------------------------------
// W2 prep (R13: cc split)
// ---------------------------------------------------------------------------
__global__ __launch_bounds__(256) void k_wprep(const float* __restrict__ w2)
{
    __shared__ float wt[128 * 81];
    const int co  = blockIdx.x;
    const int cc  = blockIdx.y;
    const int id  = threadIdx.x;
    const int c   = id & 127;
    const int hf  = id >> 7;

    const float* src = w2 + (size_t)co * 20736 + cc * 128 * 81;
    for (int i = id; i < 128 * 81; i += 256) wt[i] = src[i];
    __syncthreads();
    const int cglob = cc * 128 + c;
    const int cq    = cglob >> 6;
    const int c64   = cglob & 63;
    const uint32_t inner = swz((uint32_t)co * 128 + c64 * 2) >> 1;
    const int k0 = hf ? 41 : 0;
    const int k1 = hf ? 81 : 41;
    for (int kk = k0; kk < k1; kk++) {
        g_w2t[(size_t)(kk * 4 + cq) * 16384 + inner] =
            __float2half(wt[c * 81 + kk]);
    }
}

// ---------------------------------------------------------------------------
// conv2 implicit GEMM (unchanged R10/R12). grid 144, block 512.
// ---------------------------------------------------------------------------
#define STAGE_BYTES 49152
#define A_BYTES 32768
#define B_OFF 32768
#define MB_OFF 98304
#define NCHUNK 324

__global__ __launch_bounds__(512) void k_conv2mma(const float* __restrict__ b2)
{
    extern __shared__ __align__(1024) char dynsmem[];
    const uint32_t sb = smem_u32(dynsmem);
    const int tid  = threadIdx.x;
    const int warp = tid >> 5;
    const int lane = tid & 31;
    const int n0    = blockIdx.x * 128;
    const int mwarp = warp & 3;
    const int nwarp = warp >> 2;

    if (tid == 0) {
        MBAR_INIT(sb + MB_OFF, 1);
        MBAR_INIT(sb + MB_OFF + 8, 1);
    }
    __syncthreads();

    const int uB = tid & 7;
    int pixBase[2];
#pragma unroll
    for (int h = 0; h < 2; h++) {
        const int n    = n0 + (tid >> 3) + h * 64;
        const int bimg = n / 36;
        const int pos  = n - bimg * 36;
        const int oy   = pos / 6, ox = pos - oy * 6;
        pixBase[h] = (bimg * 400 + oy * 40 + ox * 2) * 256 + uB * 8;
    }
    uint32_t bDst[2];
    bDst[0] = swz((uint32_t)(tid >> 3) * 128 + uB * 16);
    bDst[1] = swz(((uint32_t)(tid >> 3) + 64) * 128 + uB * 16);

    const int aRowSub = lane & 15;
    const int aColSel = (lane >> 4) * 16;
    const int bMat    = lane >> 3;
    const int bSub    = lane & 7;
    const int bNfSel  = bMat >> 1;
    const int bKSel   = (bMat & 1) * 16;

    float acc[4][4][4];
#pragma unroll
    for (int mf = 0; mf < 4; mf++)
#pragma unroll
        for (int nf = 0; nf < 4; nf++)
#pragma unroll
            for (int i = 0; i < 4; i++) acc[mf][nf][i] = 0.f;

    if (tid == 0) {
        MBAR_EXPECT_TX(sb + MB_OFF, A_BYTES);
        BULK_G2S(sb, (const char*)g_w2t, A_BYTES, sb + MB_OFF);
    }
#pragma unroll
    for (int h = 0; h < 2; h++)
        CP16(sb + B_OFF + bDst[h], g_h1t + pixBase[h]);
    CP_COMMIT();

    for (int t = 0; t < NCHUNK; t++) {
        const int s = t & 1, s2 = s ^ 1;
        if (t + 1 < NCHUNK) {
            const int tn = t + 1;
            const int kk = tn >> 2, cq = tn & 3;
            if (tid == 0) {
                MBAR_EXPECT_TX(sb + MB_OFF + 8 * s2, A_BYTES);
                BULK_G2S(sb + s2 * STAGE_BYTES,
                         (const char*)(g_w2t + (size_t)tn * 16384),
                         A_BYTES, sb + MB_OFF + 8 * s2);
            }
            const int ky = kk / 9, kx = kk - ky * 9;
            const int tap  = (ky * 20 + kx) * 256;
            const int cOff = cq * 64;
#pragma unroll
            for (int h = 0; h < 2; h++)
                CP16(sb + s2 * STAGE_BYTES + B_OFF + bDst[h],
                     g_h1t + pixBase[h] + tap + cOff);
            CP_COMMIT();
            CP_WAIT1();
        } else {
            CP_WAIT0();
        }
        MBAR_WAIT(sb + MB_OFF + 8 * s, (t >> 1) & 1);
        __syncthreads();

        const uint32_t stb = sb + s * STAGE_BYTES;
        const uint32_t aa = stb;
        const uint32_t bb = stb + B_OFF;

#pragma unroll
        for (int q = 0; q < 4; q++) {
            const int qb = q * 32;
            uint32_t B[4][2];
#pragma unroll
            for (int gp = 0; gp < 2; gp++) {
                uint32_t off = swz((nwarp * 32 + (gp * 2 + bNfSel) * 8 + bSub) * 128
                                   + qb + bKSel);
                uint32_t r[4];
                ldsm_x4(r, bb + off);
                B[gp*2][0] = r[0]; B[gp*2][1] = r[1];
                B[gp*2+1][0] = r[2]; B[gp*2+1][1] = r[3];
            }
#pragma unroll
            for (int mf = 0; mf < 4; mf++) {
                uint32_t A[4];
                uint32_t offA = swz((mwarp * 64 + mf * 16 + aRowSub) * 128
                                    + qb + aColSel);
                ldsm_x4(A, aa + offA);
#pragma unroll
                for (int nf = 0; nf < 4; nf++)
                    mma16816h(acc[mf][nf], A, B[nf]);
            }
        }
        __syncthreads();
    }

#pragma unroll
    for (int mf = 0; mf < 4; mf++) {
        const int coB = mwarp * 64 + mf * 16 + (lane >> 2);
        const float bias0 = b2[coB];
        const float bias1 = b2[coB + 8];
#pragma unroll
        for (int nf = 0; nf < 4; nf++) {
#pragma unroll
            for (int i = 0; i < 4; i++) {
                const int co = coB + ((i >> 1) << 3);
                const int n  = n0 + nwarp * 32 + nf * 8 + ((lane & 3) << 1) + (i & 1);
                const int bi = n / 36;
                const int pp = n - bi * 36;
                g_h2[(size_t)bi * 9216 + co * 36 + pp] =
                    acc[mf][nf][i] + ((i >> 1) ? bias1 : bias0);
            }
        }
    }
}

// ---------------------------------------------------------------------------
// u_hat (R12 form) + FUSED primary-capsule squash. grid (288,4), block 256.
// Loads g_h2 into smem, squashes each (im,cap) octet in-place, then computes.
// ---------------------------------------------------------------------------
__global__ __launch_bounds__(256) void k_uhat(const float* __restrict__ W, int b0)
{
    __shared__ float Wsm[4 * 1280];
    __shared__ float usm[64 * 32];
    const int capg = blockIdx.x * 4;
    const int img0 = b0 + blockIdx.y * 64;
    const int id   = threadIdx.x;
    {
        const float4* Wg = (const float4*)(W + (size_t)capg * 1280);
        float4* Ws4 = (float4*)Wsm;
        for (int i = id; i < 1280; i += 256) Ws4[i] = Wg[i];
        float4* us4 = (float4*)usm;
        for (int i = id; i < 512; i += 256) {
            int im = i >> 3, r = i & 7;
            us4[i] = *(const float4*)(g_h2 + (size_t)(img0 + im) * 9216
                                      + capg * 8 + r * 4);
        }
    }
    __syncthreads();
    // fused squash: 256 threads, one (im,cap) octet each
    {
        const int im  = id >> 2;
        const int cap = id & 3;
        float* up = &usm[im * 32 + cap * 8];
        float sn = 0.f;
#pragma unroll
        for (int d = 0; d < 8; d++) sn += up[d] * up[d];
        float sc = sn / ((1.f + sn) * (sqrtf(sn) + 1e-6f));
#pragma unroll
        for (int d = 0; d < 8; d++) up[d] *= sc;
    }
    __syncthreads();

    for (int it = 0; it < 40; it++) {
        int flat = it * 256 + id;
        int oe4  = flat % 40;
        int cap  = (flat / 40) & 3;
        int im   = flat / 160;
        int o    = oe4 >> 2;
        int e0   = (oe4 & 3) * 4;
        const float*  up = &usm[im * 32 + cap * 8];
        const float4* Wp = (const float4*)&Wsm[cap * 1280 + o * 128 + e0];
        float4 acc = make_float4(0.f, 0.f, 0.f, 0.f);
#pragma unroll
        for (int d = 0; d < 8; d++) {
            float  ud = up[d];
            float4 w4 = Wp[d * 4];
            acc.x = fmaf(ud, w4.x, acc.x);
            acc.y = fmaf(ud, w4.y, acc.y);
            acc.z = fmaf(ud, w4.z, acc.z);
            acc.w = fmaf(ud, w4.w, acc.w);
        }
        __half2 h0 = __floats2half2_rn(acc.x, acc.y);
        __half2 h1 = __floats2half2_rn(acc.z, acc.w);
        uint2 pk = make_uint2(*(uint32_t*)&h0, *(uint32_t*)&h1);
        *(uint2*)&g_uhat_h[((size_t)(img0 + im) * 1152 + capg + cap) * 160
                           + o * 16 + e0] = pk;
    }
}

// ---------------------------------------------------------------------------
// fused routing iteration, b-chunked (unchanged R12)
// ---------------------------------------------------------------------------
__global__ __launch_bounds__(160) void k_route(int uniform, int b0)
{
    __shared__ __align__(16) __half tile[128 * 168];
    __shared__ float vs[160];
    __shared__ float c_sm[128][10];
    const int b     = b0 + blockIdx.x;
    const int chunk = blockIdx.y;
    const int tid   = threadIdx.x;
    const __half* ub = g_uhat_h + (size_t)b * 184320 + (size_t)chunk * 128 * 160;

    if (uniform) {
        const int oe = tid;
        float acc = 0.f;
#pragma unroll 4
        for (int cap = 0; cap < 128; cap++)
            acc += __half2float(ub[(size_t)cap * 160 + oe]);
        g_spart[((size_t)chunk * 512 + b) * 160 + oe] = acc * 0.1f;
        return;
    }

    vs[tid] = g_vsum[b * 160 + tid];
    for (int f = tid; f < 2560; f += 160) {
        const int r = f / 20, j = f % 20;
        *(uint4*)&tile[r * 168 + j * 8] = *(const uint4*)(ub + (size_t)r * 160 + j * 8);
    }
    __syncthreads();

    if (tid < 128) {
        const __half2* row = (const __half2*)&tile[tid * 168];
        float t[10];
#pragma unroll
        for (int o = 0; o < 10; o++) {
            float s = 0.f;
#pragma unroll
            for (int e2 = 0; e2 < 8; e2++) {
                float2 f = __half22float2(row[o * 8 + e2]);
                s += f.x * vs[o * 16 + e2 * 2] + f.y * vs[o * 16 + e2 * 2 + 1];
            }
            t[o] = s;
        }
        float m = t[0];
#pragma unroll
        for (int o = 1; o < 10; o++) m = fmaxf(m, t[o]);
        float se = 0.f;
#pragma unroll
        for (int o = 0; o < 10; o++) { t[o] = expf(t[o] - m); se += t[o]; }
        float inv = 1.f / se;
#pragma unroll
        for (int o = 0; o < 10; o++) c_sm[tid][o] = t[o] * inv;
    }
    __syncthreads();

    const int oe = tid;
    const int o  = oe >> 4;
    float acc = 0.f;
#pragma unroll 4
    for (int cap = 0; cap < 128; cap++)
        acc = fmaf(c_sm[cap][o], __half2float(tile[cap * 168 + oe]), acc);
    g_spart[((size_t)chunk * 512 + b) * 160 + oe] = acc;
}

// ---------------------------------------------------------------------------
// sum partials + squash, b-chunked (unchanged R12)
// ---------------------------------------------------------------------------
__global__ void k_squash_v(float* __restrict__ out, int mode, int b0)
{
    int lidx = blockIdx.x * 256 + threadIdx.x;
    if (lidx >= 2560) return;
    const size_t idx = (size_t)b0 * 10 + lidx;
    float4 r[4];
#pragma unroll
    for (int i = 0; i < 4; i++) r[i] = make_float4(0.f, 0.f, 0.f, 0.f);
#pragma unroll
    for (int p = 0; p < 9; p++) {
        const float4* sp = (const float4*)(g_spart + (size_t)p * 81920
                                           + idx * 16);
#pragma unroll
        for (int i = 0; i < 4; i++) {
            float4 v = sp[i];
            r[i].x += v.x; r[i].y += v.y; r[i].z += v.z; r[i].w += v.w;
        }
    }
    float sn = 0.f;
#pragma unroll
    for (int i = 0; i < 4; i++)
        sn += r[i].x*r[i].x + r[i].y*r[i].y + r[i].z*r[i].z + r[i].w*r[i].w;
    float sc = sn / ((1.f + sn) * (sqrtf(sn) + 1e-6f));
#pragma unroll
    for (int i = 0; i < 4; i++) {
        r[i].x *= sc; r[i].y *= sc; r[i].z *= sc; r[i].w *= sc;
    }
    if (mode == 0) {
        float4* q = (float4*)(g_vsum + idx * 16);
#pragma unroll
        for (int i = 0; i < 4; i++) q[i] = r[i];
    } else if (mode == 1) {
        float4* q = (float4*)(g_vsum + idx * 16);
#pragma unroll
        for (int i = 0; i < 4; i++) {
            float4 old = q[i];
            old.x += r[i].x; old.y += r[i].y; old.z += r[i].z; old.w += r[i].w;
            q[i] = old;
        }
    } else {
        float4* q = (float4*)(out + idx * 16);
#pragma unroll
        for (int i = 0; i < 4; i++) q[i] = r[i];
    }
}

// ---------------------------------------------------------------------------
extern "C" void kernel_launch(void* const* d_in, const int* in_sizes, int n_in,
                              void* d_out, int out_size)
{
    const float* x   = (const float*)d_in[0];
    const float* w1  = (const float*)d_in[1];
    const float* b1  = (const float*)d_in[2];
    const float* w2  = (const float*)d_in[3];
    const float* b2  = (const float*)d_in[4];
    const float* W   = (const float*)d_in[5];
    float* out = (float*)d_out;

    cudaFuncSetAttribute(k_conv1mma,
                         cudaFuncAttributeMaxDynamicSharedMemorySize, 81952);
    cudaFuncSetAttribute(k_conv2mma,
                         cudaFuncAttributeMaxDynamicSharedMemorySize, 98336);

    k_im2col<<<512, 256>>>(x);
    k_w1prep<<<256, 256>>>(w1);
    k_wprep<<<dim3(256, 2), 256>>>(w2);
    k_conv1mma<<<3200, 512, 81952>>>(b1);
    k_conv2mma<<<144, 512, 98336>>>(b2);

    for (int c = 0; c < 2; c++) {
        const int b0 = c * 256;
        k_uhat<<<dim3(288, 4), 256>>>(W, b0);
        k_route<<<dim3(256, 9), 160>>>(1, b0);
        k_squash_v<<<10, 256>>>(nullptr, 0, b0);
        k_route<<<dim3(256, 9), 160>>>(0, b0);
        k_squash_v<<<10, 256>>>(nullptr, 1, b0);
        k_route<<<dim3(256, 9), 160>>>(0, b0);
        k_squash_v<<<10, 256>>>(out, 2, b0);
    }
}

// round 15
// speedup vs baseline: 1.2355x; 1.1083x over previous
#include <cuda_runtime.h>
#include <cuda_fp16.h>
#include <cstdint>
#include <math.h>

// ===========================================================================
// CapsNet forward, B=512 — Round 15:
//  * k_uhat: Wsm o-row stride padded 128->144 floats (kills 8-way LDS bank
//    conflicts on every W float4 read in the 40-iter main loop)
//  * routing chunked 4 x 128 images (u_hat slice 47MB, guaranteed L2-resident)
//  * everything else unchanged from R14
// ===========================================================================

// ------------------------------ scratch ------------------------------------
__device__ __align__(128) __half g_x2col[512u * 400u * 256u];  // 105 MB
__device__ __align__(128) __half g_w1t [4u * 16384u];          // 128 KB
__device__ __align__(128) __half g_h1t [512u * 400u * 256u];   // 105 MB NHWC
__device__ __align__(128) __half g_w2t [81u * 4u * 16384u];    // 10.6 MB
__device__ float  g_h2[512u * 9216u];
__device__ __half g_uhat_h[512u * 1152u * 160u];               // 188.7 MB
__device__ float  g_spart[9u * 512u * 160u];
__device__ float  g_vsum[512u * 160u];

// ------------------------------ PTX helpers --------------------------------
__device__ __forceinline__ uint32_t smem_u32(const void* p) {
    uint32_t a;
    asm("{ .reg .u64 t; cvta.to.shared.u64 t, %1; cvt.u32.u64 %0, t; }"
        : "=r"(a) : "l"(p));
    return a;
}
#define CP16(dst, src) \
    asm volatile("cp.async.cg.shared.global [%0], [%1], 16;" :: "r"(dst), "l"(src) : "memory")
#define CP_COMMIT() asm volatile("cp.async.commit_group;" ::: "memory")
#define CP_WAIT1()  asm volatile("cp.async.wait_group 1;" ::: "memory")
#define CP_WAIT0()  asm volatile("cp.async.wait_group 0;" ::: "memory")

#define MBAR_INIT(a, n) \
    asm volatile("mbarrier.init.shared.b64 [%0], %1;" :: "r"(a), "r"(n) : "memory")
#define MBAR_EXPECT_TX(a, bytes) \
    asm volatile("mbarrier.arrive.expect_tx.shared.b64 _, [%0], %1;" \
                 :: "r"(a), "r"(bytes) : "memory")
#define MBAR_WAIT(a, ph) do {                                                  \
    uint32_t _m = (a), _p = (ph), _d;                                          \
    asm volatile("{ .reg .pred p;"                                             \
        "mbarrier.try_wait.parity.acquire.cta.shared::cta.b64 p, [%1], %2;"    \
        "selp.b32 %0,1,0,p; }" : "=r"(_d) : "r"(_m), "r"(_p) : "memory");      \
    if (!_d) {                                                                 \
        asm volatile("{ .reg .pred P1; WL_%=:"                                 \
            "mbarrier.try_wait.parity.acquire.cta.shared::cta.b64 P1, [%0], %1, 0x989680;" \
            "@P1 bra.uni WD_%=; bra.uni WL_%=; WD_%=: }"                       \
            :: "r"(_m), "r"(_p) : "memory");                                   \
    }                                                                          \
} while (0)
#define BULK_G2S(dst, src, size, mbar) \
    asm volatile("cp.async.bulk.shared::cta.global.mbarrier::complete_tx::bytes " \
                 "[%0], [%1], %2, [%3];" \
                 :: "r"(dst), "l"(src), "r"(size), "r"(mbar) : "memory")

__device__ __forceinline__ void ldsm_x4(uint32_t* r, uint32_t addr) {
    asm volatile("ldmatrix.sync.aligned.m8n8.x4.shared.b16 {%0,%1,%2,%3}, [%4];"
                 : "=r"(r[0]), "=r"(r[1]), "=r"(r[2]), "=r"(r[3]) : "r"(addr));
}
__device__ __forceinline__ void mma16816h(float* c, const uint32_t* a,
                                          const uint32_t* b) {
    asm volatile("mma.sync.aligned.m16n8k16.row.col.f32.f16.f16.f32 "
                 "{%0,%1,%2,%3}, {%4,%5,%6,%7}, {%8,%9}, {%0,%1,%2,%3};"
                 : "+f"(c[0]), "+f"(c[1]), "+f"(c[2]), "+f"(c[3])
                 : "r"(a[0]), "r"(a[1]), "r"(a[2]), "r"(a[3]),
                   "r"(b[0]), "r"(b[1]));
}
__device__ __forceinline__ uint32_t swz(uint32_t o) {
    return o ^ ((o >> 3) & 0x70);
}

// ---------------------------------------------------------------------------
// im2col (unchanged R12)
// ---------------------------------------------------------------------------
__global__ __launch_bounds__(256) void k_im2col(const float* __restrict__ x)
{
    __shared__ float xs[2352];
    const int b    = blockIdx.x;
    const int tid  = threadIdx.x;
    const int warp = tid >> 5;
    const int lane = tid & 31;
    {
        const float4* xg = (const float4*)(x + b * 2352);
        float4* xs4 = (float4*)xs;
        for (int i = tid; i < 588; i += 256) xs4[i] = xg[i];
    }
    int l[8];
#pragma unroll
    for (int j = 0; j < 8; j++) {
        const int k = lane * 8 + j;
        if (k < 243) {
            const int c = k / 81, kk = k - c * 81;
            const int ky = kk / 9, kx = kk - ky * 9;
            l[j] = c * 784 + ky * 28 + kx;
        } else l[j] = -1;
    }
    __syncthreads();

    for (int p = warp; p < 400; p += 8) {
        const int oy = p / 20, ox = p - (p / 20) * 20;
        const int off = oy * 28 + ox;
        __align__(16) __half vals[8];
#pragma unroll
        for (int j = 0; j < 8; j++)
            vals[j] = (l[j] >= 0) ? __float2half(xs[l[j] + off]) : __half(0.f);
        *(uint4*)&g_x2col[((size_t)b * 400 + p) * 256 + lane * 8] =
            *(const uint4*)vals;
    }
}

// ---------------------------------------------------------------------------
// w1 prep (unchanged R12)
// ---------------------------------------------------------------------------
__global__ __launch_bounds__(256) void k_w1prep(const float* __restrict__ w1)
{
    const int co = blockIdx.x;
    const int k  = threadIdx.x;
    float v = (k < 243) ? w1[co * 243 + k] : 0.f;
    const int cq  = k >> 6;
    const int k64 = k & 63;
    const uint32_t inner = swz((uint32_t)co * 128 + k64 * 2) >> 1;
    g_w1t[cq * 16384 + inner] = __float2half(v);
}

// ---------------------------------------------------------------------------
// conv1 GEMM: M=256 co x N=64 pos. grid 3200, block 512, 2 CTA/SM (R13).
// ---------------------------------------------------------------------------
#define C1_STAGE 40960
#define C1_B_OFF 32768
#define C1_MB    81920
#define C1_NCH   4

__global__ __launch_bounds__(512, 2) void k_conv1mma(const float* __restrict__ b1)
{
    extern __shared__ __align__(1024) char dynsmem[];
    const uint32_t sb = smem_u32(dynsmem);
    const int tid  = threadIdx.x;
    const int warp = tid >> 5;
    const int lane = tid & 31;
    const int n0    = blockIdx.x * 64;
    const int mwarp = warp & 3;
    const int nwarp = warp >> 2;

    if (tid == 0) {
        MBAR_INIT(sb + C1_MB, 1);
        MBAR_INIT(sb + C1_MB + 8, 1);
    }
    __syncthreads();

    const int uB   = tid & 7;
    const int row0 = tid >> 3;
    const uint32_t pixBase = (uint32_t)(n0 + row0) * 256u + uB * 8;
    const uint32_t bDst    = swz((uint32_t)row0 * 128 + uB * 16);

    const int aRowSub = lane & 15;
    const int aColSel = (lane >> 4) * 16;
    const int bMat    = lane >> 3;
    const int bSub    = lane & 7;
    const int bNfSel  = bMat >> 1;
    const int bKSel   = (bMat & 1) * 16;

    float acc[4][2][4];
#pragma unroll
    for (int mf = 0; mf < 4; mf++)
#pragma unroll
        for (int nf = 0; nf < 2; nf++)
#pragma unroll
            for (int i = 0; i < 4; i++) acc[mf][nf][i] = 0.f;

    if (tid == 0) {
        MBAR_EXPECT_TX(sb + C1_MB, 32768);
        BULK_G2S(sb, (const char*)g_w1t, 32768, sb + C1_MB);
    }
    CP16(sb + C1_B_OFF + bDst, g_x2col + pixBase);
    CP_COMMIT();

    for (int t = 0; t < C1_NCH; t++) {
        const int s = t & 1, s2 = s ^ 1;
        if (t + 1 < C1_NCH) {
            const int tn = t + 1;
            if (tid == 0) {
                MBAR_EXPECT_TX(sb + C1_MB + 8 * s2, 32768);
                BULK_G2S(sb + s2 * C1_STAGE,
                         (const char*)(g_w1t + (size_t)tn * 16384),
                         32768, sb + C1_MB + 8 * s2);
            }
            CP16(sb + s2 * C1_STAGE + C1_B_OFF + bDst,
                 g_x2col + pixBase + tn * 64);
            CP_COMMIT();
            CP_WAIT1();
        } else {
            CP_WAIT0();
        }
        MBAR_WAIT(sb + C1_MB + 8 * s, (t >> 1) & 1);
        __syncthreads();

        const uint32_t stb = sb + s * C1_STAGE;
        const uint32_t aa = stb;
        const uint32_t bb = stb + C1_B_OFF;

#pragma unroll
        for (int q = 0; q < 4; q++) {
            const int qb = q * 32;
            uint32_t B[2][2];
            {
                uint32_t off = swz((nwarp * 16 + bNfSel * 8 + bSub) * 128
                                   + qb + bKSel);
                uint32_t r[4];
                ldsm_x4(r, bb + off);
                B[0][0] = r[0]; B[0][1] = r[1];
                B[1][0] = r[2]; B[1][1] = r[3];
            }
#pragma unroll
            for (int mf = 0; mf < 4; mf++) {
                uint32_t A[4];
                uint32_t offA = swz((mwarp * 64 + mf * 16 + aRowSub) * 128
                                    + qb + aColSel);
                ldsm_x4(A, aa + offA);
#pragma unroll
                for (int nf = 0; nf < 2; nf++)
                    mma16816h(acc[mf][nf], A, B[nf]);
            }
        }
        __syncthreads();
    }

    __half* ebuf = (__half*)dynsmem;
#pragma unroll
    for (int mf = 0; mf < 4; mf++) {
        const int coB = mwarp * 64 + mf * 16 + (lane >> 2);
        const float bias0 = b1[coB];
        const float bias1 = b1[coB + 8];
#pragma unroll
        for (int nf = 0; nf < 2; nf++) {
#pragma unroll
            for (int i = 0; i < 4; i++) {
                const int co = coB + ((i >> 1) << 3);
                const int nl = nwarp * 16 + nf * 8 + ((lane & 3) << 1) + (i & 1);
                const float v = acc[mf][nf][i] + ((i >> 1) ? bias1 : bias0);
                ebuf[nl * 256 + co] = __float2half(fmaxf(v, 0.f));
            }
        }
    }
    __syncthreads();
    for (int f = tid; f < 64 * 32; f += 512) {
        const int rw = f >> 5;
        const int j  = f & 31;
        *(uint4*)&g_h1t[(size_t)(n0 + rw) * 256 + j * 8] =
            *(const uint4*)&ebuf[rw * 256 + j * 8];
    }
}

// ---------------------------------------------------------------------------
// W2 prep (R13 cc split)
// ---------------------------------------------------------------------------
__global__ __launch_bounds__(256) void k_wprep(const float* __restrict__ w2)
{
    __shared__ float wt[128 * 81];
    const int co  = blockIdx.x;
    const int cc  = blockIdx.y;
    const int id  = threadIdx.x;
    const int c   = id & 127;
    const int hf  = id >> 7;

    const float* src = w2 + (size_t)co * 20736 + cc * 128 * 81;
    for (int i = id; i < 128 * 81; i += 256) wt[i] = src[i];
    __syncthreads();
    const int cglob = cc * 128 + c;
    const int cq    = cglob >> 6;
    const int c64   = cglob & 63;
    const uint32_t inner = swz((uint32_t)co * 128 + c64 * 2) >> 1;
    const int k0 = hf ? 41 : 0;
    const int k1 = hf ? 81 : 41;
    for (int kk = k0; kk < k1; kk++) {
        g_w2t[(size_t)(kk * 4 + cq) * 16384 + inner] =
            __float2half(wt[c * 81 + kk]);
    }
}

// ---------------------------------------------------------------------------
// conv2 implicit GEMM (unchanged R10/R12). grid 144, block 512.
// ---------------------------------------------------------------------------
#define STAGE_BYTES 49152
#define A_BYTES 32768
#define B_OFF 32768
#define MB_OFF 98304
#define NCHUNK 324

__global__ __launch_bounds__(512) void k_conv2mma(const float* __restrict__ b2)
{
    extern __shared__ __align__(1024) char dynsmem[];
    const uint32_t sb = smem_u32(dynsmem);
    const int tid  = threadIdx.x;
    const int warp = tid >> 5;
    const int lane = tid & 31;
    const int n0    = blockIdx.x * 128;
    const int mwarp = warp & 3;
    const int nwarp = warp >> 2;

    if (tid == 0) {
        MBAR_INIT(sb + MB_OFF, 1);
        MBAR_INIT(sb + MB_OFF + 8, 1);
    }
    __syncthreads();

    const int uB = tid & 7;
    int pixBase[2];
#pragma unroll
    for (int h = 0; h < 2; h++) {
        const int n    = n0 + (tid >> 3) + h * 64;
        const int bimg = n / 36;
        const int pos  = n - bimg * 36;
        const int oy   = pos / 6, ox = pos - oy * 6;
        pixBase[h] = (bimg * 400 + oy * 40 + ox * 2) * 256 + uB * 8;
    }
    uint32_t bDst[2];
    bDst[0] = swz((uint32_t)(tid >> 3) * 128 + uB * 16);
    bDst[1] = swz(((uint32_t)(tid >> 3) + 64) * 128 + uB * 16);

    const int aRowSub = lane & 15;
    const int aColSel = (lane >> 4) * 16;
    const int bMat    = lane >> 3;
    const int bSub    = lane & 7;
    const int bNfSel  = bMat >> 1;
    const int bKSel   = (bMat & 1) * 16;

    float acc[4][4][4];
#pragma unroll
    for (int mf = 0; mf < 4; mf++)
#pragma unroll
        for (int nf = 0; nf < 4; nf++)
#pragma unroll
            for (int i = 0; i < 4; i++) acc[mf][nf][i] = 0.f;

    if (tid == 0) {
        MBAR_EXPECT_TX(sb + MB_OFF, A_BYTES);
        BULK_G2S(sb, (const char*)g_w2t, A_BYTES, sb + MB_OFF);
    }
#pragma unroll
    for (int h = 0; h < 2; h++)
        CP16(sb + B_OFF + bDst[h], g_h1t + pixBase[h]);
    CP_COMMIT();

    for (int t = 0; t < NCHUNK; t++) {
        const int s = t & 1, s2 = s ^ 1;
        if (t + 1 < NCHUNK) {
            const int tn = t + 1;
            const int kk = tn >> 2, cq = tn & 3;
            if (tid == 0) {
                MBAR_EXPECT_TX(sb + MB_OFF + 8 * s2, A_BYTES);
                BULK_G2S(sb + s2 * STAGE_BYTES,
                         (const char*)(g_w2t + (size_t)tn * 16384),
                         A_BYTES, sb + MB_OFF + 8 * s2);
            }
            const int ky = kk / 9, kx = kk - ky * 9;
            const int tap  = (ky * 20 + kx) * 256;
            const int cOff = cq * 64;
#pragma unroll
            for (int h = 0; h < 2; h++)
                CP16(sb + s2 * STAGE_BYTES + B_OFF + bDst[h],
                     g_h1t + pixBase[h] + tap + cOff);
            CP_COMMIT();
            CP_WAIT1();
        } else {
            CP_WAIT0();
        }
        MBAR_WAIT(sb + MB_OFF + 8 * s, (t >> 1) & 1);
        __syncthreads();

        const uint32_t stb = sb + s * STAGE_BYTES;
        const uint32_t aa = stb;
        const uint32_t bb = stb + B_OFF;

#pragma unroll
        for (int q = 0; q < 4; q++) {
            const int qb = q * 32;
            uint32_t B[4][2];
#pragma unroll
            for (int gp = 0; gp < 2; gp++) {
                uint32_t off = swz((nwarp * 32 + (gp * 2 + bNfSel) * 8 + bSub) * 128
                                   + qb + bKSel);
                uint32_t r[4];
                ldsm_x4(r, bb + off);
                B[gp*2][0] = r[0]; B[gp*2][1] = r[1];
                B[gp*2+1][0] = r[2]; B[gp*2+1][1] = r[3];
            }
#pragma unroll
            for (int mf = 0; mf < 4; mf++) {
                uint32_t A[4];
                uint32_t offA = swz((mwarp * 64 + mf * 16 + aRowSub) * 128
                                    + qb + aColSel);
                ldsm_x4(A, aa + offA);
#pragma unroll
                for (int nf = 0; nf < 4; nf++)
                    mma16816h(acc[mf][nf], A, B[nf]);
            }
        }
        __syncthreads();
    }

#pragma unroll
    for (int mf = 0; mf < 4; mf++) {
        const int coB = mwarp * 64 + mf * 16 + (lane >> 2);
        const float bias0 = b2[coB];
        const float bias1 = b2[coB + 8];
#pragma unroll
        for (int nf = 0; nf < 4; nf++) {
#pragma unroll
            for (int i = 0; i < 4; i++) {
                const int co = coB + ((i >> 1) << 3);
                const int n  = n0 + nwarp * 32 + nf * 8 + ((lane & 3) << 1) + (i & 1);
                const int bi = n / 36;
                const int pp = n - bi * 36;
                g_h2[(size_t)bi * 9216 + co * 36 + pp] =
                    acc[mf][nf][i] + ((i >> 1) ? bias1 : bias0);
            }
        }
    }
}

// ---------------------------------------------------------------------------
// u_hat + fused primary squash. grid (288, nimg/64), block 256.
// Wsm padded: o-row stride 144 floats (cap stride 1440) — conflict-free LDS.
// ---------------------------------------------------------------------------
__global__ __launch_bounds__(256) void k_uhat(const float* __restrict__ W, int b0)
{
    __shared__ float Wsm[4 * 1440];     // padded: [cap][o:10][144]
    __shared__ float usm[64 * 32];
    const int capg = blockIdx.x * 4;
    const int img0 = b0 + blockIdx.y * 64;
    const int id   = threadIdx.x;
    {
        const float4* Wg = (const float4*)(W + (size_t)capg * 1280);
        float4* Ws4 = (float4*)Wsm;
        for (int i = id; i < 1280; i += 256) {
            const int cap = i / 320;
            const int rem = i - cap * 320;
            const int o   = rem / 32;
            const int e4  = rem - o * 32;
            Ws4[cap * 360 + o * 36 + e4] = Wg[i];
        }
        float4* us4 = (float4*)usm;
        for (int i = id; i < 512; i += 256) {
            int im = i >> 3, r = i & 7;
            us4[i] = *(const float4*)(g_h2 + (size_t)(img0 + im) * 9216
                                      + capg * 8 + r * 4);
        }
    }
    __syncthreads();
    // fused squash: 256 threads, one (im,cap) octet each
    {
        const int im  = id >> 2;
        const int cap = id & 3;
        float* up = &usm[im * 32 + cap * 8];
        float sn = 0.f;
#pragma unroll
        for (int d = 0; d < 8; d++) sn += up[d] * up[d];
        float sc = sn / ((1.f + sn) * (sqrtf(sn) + 1e-6f));
#pragma unroll
        for (int d = 0; d < 8; d++) up[d] *= sc;
    }
    __syncthreads();

    for (int it = 0; it < 40; it++) {
        int flat = it * 256 + id;
        int oe4  = flat % 40;
        int cap  = (flat / 40) & 3;
        int im   = flat / 160;
        int o    = oe4 >> 2;
        int e0   = (oe4 & 3) * 4;
        const float*  up = &usm[im * 32 + cap * 8];
        const float4* Wp = (const float4*)&Wsm[cap * 1440 + o * 144 + e0];
        float4 acc = make_float4(0.f, 0.f, 0.f, 0.f);
#pragma unroll
        for (int d = 0; d < 8; d++) {
            float  ud = up[d];
            float4 w4 = Wp[d * 4];
            acc.x = fmaf(ud, w4.x, acc.x);
            acc.y = fmaf(ud, w4.y, acc.y);
            acc.z = fmaf(ud, w4.z, acc.z);
            acc.w = fmaf(ud, w4.w, acc.w);
        }
        __half2 h0 = __floats2half2_rn(acc.x, acc.y);
        __half2 h1 = __floats2half2_rn(acc.z, acc.w);
        uint2 pk = make_uint2(*(uint32_t*)&h0, *(uint32_t*)&h1);
        *(uint2*)&g_uhat_h[((size_t)(img0 + im) * 1152 + capg + cap) * 160
                           + o * 16 + e0] = pk;
    }
}

// ---------------------------------------------------------------------------
// fused routing iteration, b-chunked (unchanged logic)
// ---------------------------------------------------------------------------
__global__ __launch_bounds__(160) void k_route(int uniform, int b0)
{
    __shared__ __align__(16) __half tile[128 * 168];
    __shared__ float vs[160];
    __shared__ float c_sm[128][10];
    const int b     = b0 + blockIdx.x;
    const int chunk = blockIdx.y;
    const int tid   = threadIdx.x;
    const __half* ub = g_uhat_h + (size_t)b * 184320 + (size_t)chunk * 128 * 160;

    if (uniform) {
        const int oe = tid;
        float acc = 0.f;
#pragma unroll 4
        for (int cap = 0; cap < 128; cap++)
            acc += __half2float(ub[(size_t)cap * 160 + oe]);
        g_spart[((size_t)chunk * 512 + b) * 160 + oe] = acc * 0.1f;
        return;
    }

    vs[tid] = g_vsum[b * 160 + tid];
    for (int f = tid; f < 2560; f += 160) {
        const int r = f / 20, j = f % 20;
        *(uint4*)&tile[r * 168 + j * 8] = *(const uint4*)(ub + (size_t)r * 160 + j * 8);
    }
    __syncthreads();

    if (tid < 128) {
        const __half2* row = (const __half2*)&tile[tid * 168];
        float t[10];
#pragma unroll
        for (int o = 0; o < 10; o++) {
            float s = 0.f;
#pragma unroll
            for (int e2 = 0; e2 < 8; e2++) {
                float2 f = __half22float2(row[o * 8 + e2]);
                s += f.x * vs[o * 16 + e2 * 2] + f.y * vs[o * 16 + e2 * 2 + 1];
            }
            t[o] = s;
        }
        float m = t[0];
#pragma unroll
        for (int o = 1; o < 10; o++) m = fmaxf(m, t[o]);
        float se = 0.f;
#pragma unroll
        for (int o = 0; o < 10; o++) { t[o] = expf(t[o] - m); se += t[o]; }
        float inv = 1.f / se;
#pragma unroll
        for (int o = 0; o < 10; o++) c_sm[tid][o] = t[o] * inv;
    }
    __syncthreads();

    const int oe = tid;
    const int o  = oe >> 4;
    float acc = 0.f;
#pragma unroll 4
    for (int cap = 0; cap < 128; cap++)
        acc = fmaf(c_sm[cap][o], __half2float(tile[cap * 168 + oe]), acc);
    g_spart[((size_t)chunk * 512 + b) * 160 + oe] = acc;
}

// ---------------------------------------------------------------------------
// sum partials + squash, b-chunked (128 imgs -> 1280 pairs, grid 5)
// ---------------------------------------------------------------------------
__global__ void k_squash_v(float* __restrict__ out, int mode, int b0, int npair)
{
    int lidx = blockIdx.x * 256 + threadIdx.x;
    if (lidx >= npair) return;
    const size_t idx = (size_t)b0 * 10 + lidx;
    float4 r[4];
#pragma unroll
    for (int i = 0; i < 4; i++) r[i] = make_float4(0.f, 0.f, 0.f, 0.f);
#pragma unroll
    for (int p = 0; p < 9; p++) {
        const float4* sp = (const float4*)(g_spart + (size_t)p * 81920
                                           + idx * 16);
#pragma unroll
        for (int i = 0; i < 4; i++) {
            float4 v = sp[i];
            r[i].x += v.x; r[i].y += v.y; r[i].z += v.z; r[i].w += v.w;
        }
    }
    float sn = 0.f;
#pragma unroll
    for (int i = 0; i < 4; i++)
        sn += r[i].x*r[i].x + r[i].y*r[i].y + r[i].z*r[i].z + r[i].w*r[i].w;
    float sc = sn / ((1.f + sn) * (sqrtf(sn) + 1e-6f));
#pragma unroll
    for (int i = 0; i < 4; i++) {
        r[i].x *= sc; r[i].y *= sc; r[i].z *= sc; r[i].w *= sc;
    }
    if (mode == 0) {
        float4* q = (float4*)(g_vsum + idx * 16);
#pragma unroll
        for (int i = 0; i < 4; i++) q[i] = r[i];
    } else if (mode == 1) {
        float4* q = (float4*)(g_vsum + idx * 16);
#pragma unroll
        for (int i = 0; i < 4; i++) {
            float4 old = q[i];
            old.x += r[i].x; old.y += r[i].y; old.z += r[i].z; old.w += r[i].w;
            q[i] = old;
        }
    } else {
        float4* q = (float4*)(out + idx * 16);
#pragma unroll
        for (int i = 0; i < 4; i++) q[i] = r[i];
    }
}

// ---------------------------------------------------------------------------
extern "C" void kernel_launch(void* const* d_in, const int* in_sizes, int n_in,
                              void* d_out, int out_size)
{
    const float* x   = (const float*)d_in[0];
    const float* w1  = (const float*)d_in[1];
    const float* b1  = (const float*)d_in[2];
    const float* w2  = (const float*)d_in[3];
    const float* b2  = (const float*)d_in[4];
    const float* W   = (const float*)d_in[5];
    float* out = (float*)d_out;

    cudaFuncSetAttribute(k_conv1mma,
                         cudaFuncAttributeMaxDynamicSharedMemorySize, 81952);
    cudaFuncSetAttribute(k_conv2mma,
                         cudaFuncAttributeMaxDynamicSharedMemorySize, 98336);

    k_im2col<<<512, 256>>>(x);
    k_w1prep<<<256, 256>>>(w1);
    k_wprep<<<dim3(256, 2), 256>>>(w2);
    k_conv1mma<<<3200, 512, 81952>>>(b1);
    k_conv2mma<<<144, 512, 98336>>>(b2);

    // routing tail, 4 x 128-image chunks (u_hat slice 47 MB, L2-resident)
    for (int c = 0; c < 4; c++) {
        const int b0 = c * 128;
        k_uhat<<<dim3(288, 2), 256>>>(W, b0);
        k_route<<<dim3(128, 9), 160>>>(1, b0);
        k_squash_v<<<5, 256>>>(nullptr, 0, b0, 1280);
        k_route<<<dim3(128, 9), 160>>>(0, b0);
        k_squash_v<<<5, 256>>>(nullptr, 1, b0, 1280);
        k_route<<<dim3(128, 9), 160>>>(0, b0);
        k_squash_v<<<5, 256>>>(out, 2, b0, 1280);
    }
}

// round 16
// speedup vs baseline: 1.2356x; 1.0001x over previous
#include <cuda_runtime.h>
#include <cuda_fp16.h>
#include <cstdint>
#include <math.h>

// ===========================================================================
// CapsNet forward, B=512 — Round 16: im2col fused into conv1mma (k_im2col
// and g_x2col deleted; B fragments gathered from raw x in smem, bit-identical
// values). Everything else unchanged from R15.
// ===========================================================================

// ------------------------------ scratch ------------------------------------
__device__ __align__(128) __half g_w1t [4u * 16384u];          // 128 KB
__device__ __align__(128) __half g_h1t [512u * 400u * 256u];   // 105 MB NHWC
__device__ __align__(128) __half g_w2t [81u * 4u * 16384u];    // 10.6 MB
__device__ float  g_h2[512u * 9216u];
__device__ __half g_uhat_h[512u * 1152u * 160u];               // 188.7 MB
__device__ float  g_spart[9u * 512u * 160u];
__device__ float  g_vsum[512u * 160u];

// ------------------------------ PTX helpers --------------------------------
__device__ __forceinline__ uint32_t smem_u32(const void* p) {
    uint32_t a;
    asm("{ .reg .u64 t; cvta.to.shared.u64 t, %1; cvt.u32.u64 %0, t; }"
        : "=r"(a) : "l"(p));
    return a;
}
#define CP16(dst, src) \
    asm volatile("cp.async.cg.shared.global [%0], [%1], 16;" :: "r"(dst), "l"(src) : "memory")
#define CP_COMMIT() asm volatile("cp.async.commit_group;" ::: "memory")
#define CP_WAIT1()  asm volatile("cp.async.wait_group 1;" ::: "memory")
#define CP_WAIT0()  asm volatile("cp.async.wait_group 0;" ::: "memory")

#define MBAR_INIT(a, n) \
    asm volatile("mbarrier.init.shared.b64 [%0], %1;" :: "r"(a), "r"(n) : "memory")
#define MBAR_EXPECT_TX(a, bytes) \
    asm volatile("mbarrier.arrive.expect_tx.shared.b64 _, [%0], %1;" \
                 :: "r"(a), "r"(bytes) : "memory")
#define MBAR_WAIT(a, ph) do {                                                  \
    uint32_t _m = (a), _p = (ph), _d;                                          \
    asm volatile("{ .reg .pred p;"                                             \
        "mbarrier.try_wait.parity.acquire.cta.shared::cta.b64 p, [%1], %2;"    \
        "selp.b32 %0,1,0,p; }" : "=r"(_d) : "r"(_m), "r"(_p) : "memory");      \
    if (!_d) {                                                                 \
        asm volatile("{ .reg .pred P1; WL_%=:"                                 \
            "mbarrier.try_wait.parity.acquire.cta.shared::cta.b64 P1, [%0], %1, 0x989680;" \
            "@P1 bra.uni WD_%=; bra.uni WL_%=; WD_%=: }"                       \
            :: "r"(_m), "r"(_p) : "memory");                                   \
    }                                                                          \
} while (0)
#define BULK_G2S(dst, src, size, mbar) \
    asm volatile("cp.async.bulk.shared::cta.global.mbarrier::complete_tx::bytes " \
                 "[%0], [%1], %2, [%3];" \
                 :: "r"(dst), "l"(src), "r"(size), "r"(mbar) : "memory")

__device__ __forceinline__ void ldsm_x4(uint32_t* r, uint32_t addr) {
    asm volatile("ldmatrix.sync.aligned.m8n8.x4.shared.b16 {%0,%1,%2,%3}, [%4];"
                 : "=r"(r[0]), "=r"(r[1]), "=r"(r[2]), "=r"(r[3]) : "r"(addr));
}
__device__ __forceinline__ void mma16816h(float* c, const uint32_t* a,
                                          const uint32_t* b) {
    asm volatile("mma.sync.aligned.m16n8k16.row.col.f32.f16.f16.f32 "
                 "{%0,%1,%2,%3}, {%4,%5,%6,%7}, {%8,%9}, {%0,%1,%2,%3};"
                 : "+f"(c[0]), "+f"(c[1]), "+f"(c[2]), "+f"(c[3])
                 : "r"(a[0]), "r"(a[1]), "r"(a[2]), "r"(a[3]),
                   "r"(b[0]), "r"(b[1]));
}
__device__ __forceinline__ uint32_t swz(uint32_t o) {
    return o ^ ((o >> 3) & 0x70);
}

// ---------------------------------------------------------------------------
// w1 prep (unchanged)
// ---------------------------------------------------------------------------
__global__ __launch_bounds__(256) void k_w1prep(const float* __restrict__ w1)
{
    const int co = blockIdx.x;
    const int k  = threadIdx.x;
    float v = (k < 243) ? w1[co * 243 + k] : 0.f;
    const int cq  = k >> 6;
    const int k64 = k & 63;
    const uint32_t inner = swz((uint32_t)co * 128 + k64 * 2) >> 1;
    g_w1t[cq * 16384 + inner] = __float2half(v);
}

// ---------------------------------------------------------------------------
// conv1 GEMM with fused im2col. grid 3200, block 512, 2 CTA/SM.
// smem: stages[2 x 40960] | mbar@81920 | lut@81936 (256 int) | xs@82960
// (2 x 2352 float). B fragments gathered from xs via LUT + STS.128.
// ---------------------------------------------------------------------------
#define C1_STAGE 40960
#define C1_B_OFF 32768
#define C1_MB    81920
#define C1_LUT   81936
#define C1_XS    82960
#define C1_SMEM  101776
#define C1_NCH   4

__global__ __launch_bounds__(512, 2) void k_conv1mma(const float* __restrict__ x,
                                                     const float* __restrict__ b1)
{
    extern __shared__ __align__(1024) char dynsmem[];
    const uint32_t sb = smem_u32(dynsmem);
    int*   lut = (int*)(dynsmem + C1_LUT);
    float* xs  = (float*)(dynsmem + C1_XS);
    const int tid  = threadIdx.x;
    const int warp = tid >> 5;
    const int lane = tid & 31;
    const int n0    = blockIdx.x * 64;
    const int mwarp = warp & 3;
    const int nwarp = warp >> 2;

    if (tid == 0) {
        MBAR_INIT(sb + C1_MB, 1);
        MBAR_INIT(sb + C1_MB + 8, 1);
    }
    // LUT: k -> xs offset (-1 for pad)
    if (tid < 256) {
        const int k = tid;
        if (k < 243) {
            const int c = k / 81, kk = k - c * 81;
            const int ky = kk / 9, kx = kk - ky * 9;
            lut[k] = c * 784 + ky * 28 + kx;
        } else lut[k] = -1;
    }
    // load the <=2 source images covering positions n0..n0+63
    {
        const int im0 = n0 / 400;
        const int im1 = (n0 + 63) / 400;
        const float4* s0 = (const float4*)(x + im0 * 2352);
        const float4* s1 = (const float4*)(x + im1 * 2352);
        float4* d = (float4*)xs;
        for (int i = tid; i < 588; i += 512) {
            d[i]       = s0[i];
            d[i + 588] = s1[i];
        }
    }
    __syncthreads();

    // B stager role: pos = n0+row0, k-octet uB
    const int uB   = tid & 7;
    const int row0 = tid >> 3;
    const int pos  = n0 + row0;
    const int im   = pos / 400;
    const int imSel = im - n0 / 400;              // 0 or 1
    const int p400  = pos - im * 400;
    const int xoff  = imSel * 2352 + (p400 / 20) * 28 + (p400 % 20);
    const uint32_t bDst = swz((uint32_t)row0 * 128 + uB * 16);

    const int aRowSub = lane & 15;
    const int aColSel = (lane >> 4) * 16;
    const int bMat    = lane >> 3;
    const int bSub    = lane & 7;
    const int bNfSel  = bMat >> 1;
    const int bKSel   = (bMat & 1) * 16;

    float acc[4][2][4];
#pragma unroll
    for (int mf = 0; mf < 4; mf++)
#pragma unroll
        for (int nf = 0; nf < 2; nf++)
#pragma unroll
            for (int i = 0; i < 4; i++) acc[mf][nf][i] = 0.f;

    if (tid == 0) {
        MBAR_EXPECT_TX(sb + C1_MB, 32768);
        BULK_G2S(sb, (const char*)g_w1t, 32768, sb + C1_MB);
    }
    // prologue: gather B chunk 0 -> stage 0
    {
        const int k0 = uB * 8;
        __align__(16) __half vals[8];
#pragma unroll
        for (int j = 0; j < 8; j++) {
            const int lk = lut[k0 + j];
            vals[j] = (lk >= 0) ? __float2half(xs[lk + xoff]) : __half(0.f);
        }
        *(uint4*)(dynsmem + (C1_B_OFF + bDst)) = *(const uint4*)vals;
    }

    for (int t = 0; t < C1_NCH; t++) {
        const int s = t & 1, s2 = s ^ 1;
        if (t + 1 < C1_NCH) {
            const int tn = t + 1;
            if (tid == 0) {
                MBAR_EXPECT_TX(sb + C1_MB + 8 * s2, 32768);
                BULK_G2S(sb + s2 * C1_STAGE,
                         (const char*)(g_w1t + (size_t)tn * 16384),
                         32768, sb + C1_MB + 8 * s2);
            }
            const int k0 = tn * 64 + uB * 8;
            __align__(16) __half vals[8];
#pragma unroll
            for (int j = 0; j < 8; j++) {
                const int lk = lut[k0 + j];
                vals[j] = (lk >= 0) ? __float2half(xs[lk + xoff]) : __half(0.f);
            }
            *(uint4*)(dynsmem + (s2 * C1_STAGE + C1_B_OFF + bDst)) =
                *(const uint4*)vals;
        }
        MBAR_WAIT(sb + C1_MB + 8 * s, (t >> 1) & 1);
        __syncthreads();

        const uint32_t stb = sb + s * C1_STAGE;
        const uint32_t aa = stb;
        const uint32_t bb = stb + C1_B_OFF;

#pragma unroll
        for (int q = 0; q < 4; q++) {
            const int qb = q * 32;
            uint32_t B[2][2];
            {
                uint32_t off = swz((nwarp * 16 + bNfSel * 8 + bSub) * 128
                                   + qb + bKSel);
                uint32_t r[4];
                ldsm_x4(r, bb + off);
                B[0][0] = r[0]; B[0][1] = r[1];
                B[1][0] = r[2]; B[1][1] = r[3];
            }
#pragma unroll
            for (int mf = 0; mf < 4; mf++) {
                uint32_t A[4];
                uint32_t offA = swz((mwarp * 64 + mf * 16 + aRowSub) * 128
                                    + qb + aColSel);
                ldsm_x4(A, aa + offA);
#pragma unroll
                for (int nf = 0; nf < 2; nf++)
                    mma16816h(acc[mf][nf], A, B[nf]);
            }
        }
        __syncthreads();
    }

    // epilogue: bias + relu + fp16 via smem transpose -> coalesced h1t rows
    __half* ebuf = (__half*)dynsmem;
#pragma unroll
    for (int mf = 0; mf < 4; mf++) {
        const int coB = mwarp * 64 + mf * 16 + (lane >> 2);
        const float bias0 = b1[coB];
        const float bias1 = b1[coB + 8];
#pragma unroll
        for (int nf = 0; nf < 2; nf++) {
#pragma unroll
            for (int i = 0; i < 4; i++) {
                const int co = coB + ((i >> 1) << 3);
                const int nl = nwarp * 16 + nf * 8 + ((lane & 3) << 1) + (i & 1);
                const float v = acc[mf][nf][i] + ((i >> 1) ? bias1 : bias0);
                ebuf[nl * 256 + co] = __float2half(fmaxf(v, 0.f));
            }
        }
    }
    __syncthreads();
    for (int f = tid; f < 64 * 32; f += 512) {
        const int rw = f >> 5;
        const int j  = f & 31;
        *(uint4*)&g_h1t[(size_t)(n0 + rw) * 256 + j * 8] =
            *(const uint4*)&ebuf[rw * 256 + j * 8];
    }
}

// ---------------------------------------------------------------------------
// W2 prep (unchanged R13)
// ---------------------------------------------------------------------------
__global__ __launch_bounds__(256) void k_wprep(const float* __restrict__ w2)
{
    __shared__ float wt[128 * 81];
    const int co  = blockIdx.x;
    const int cc  = blockIdx.y;
    const int id  = threadIdx.x;
    const int c   = id & 127;
    const int hf  = id >> 7;

    const float* src = w2 + (size_t)co * 20736 + cc * 128 * 81;
    for (int i = id; i < 128 * 81; i += 256) wt[i] = src[i];
    __syncthreads();
    const int cglob = cc * 128 + c;
    const int cq    = cglob >> 6;
    const int c64   = cglob & 63;
    const uint32_t inner = swz((uint32_t)co * 128 + c64 * 2) >> 1;
    const int k0 = hf ? 41 : 0;
    const int k1 = hf ? 81 : 41;
    for (int kk = k0; kk < k1; kk++) {
        g_w2t[(size_t)(kk * 4 + cq) * 16384 + inner] =
            __float2half(wt[c * 81 + kk]);
    }
}

// ---------------------------------------------------------------------------
// conv2 implicit GEMM (unchanged). grid 144, block 512.
// ---------------------------------------------------------------------------
#define STAGE_BYTES 49152
#define A_BYTES 32768
#define B_OFF 32768
#define MB_OFF 98304
#define NCHUNK 324

__global__ __launch_bounds__(512) void k_conv2mma(const float* __restrict__ b2)
{
    extern __shared__ __align__(1024) char dynsmem[];
    const uint32_t sb = smem_u32(dynsmem);
    const int tid  = threadIdx.x;
    const int warp = tid >> 5;
    const int lane = tid & 31;
    const int n0    = blockIdx.x * 128;
    const int mwarp = warp & 3;
    const int nwarp = warp >> 2;

    if (tid == 0) {
        MBAR_INIT(sb + MB_OFF, 1);
        MBAR_INIT(sb + MB_OFF + 8, 1);
    }
    __syncthreads();

    const int uB = tid & 7;
    int pixBase[2];
#pragma unroll
    for (int h = 0; h < 2; h++) {
        const int n    = n0 + (tid >> 3) + h * 64;
        const int bimg = n / 36;
        const int pos  = n - bimg * 36;
        const int oy   = pos / 6, ox = pos - oy * 6;
        pixBase[h] = (bimg * 400 + oy * 40 + ox * 2) * 256 + uB * 8;
    }
    uint32_t bDst[2];
    bDst[0] = swz((uint32_t)(tid >> 3) * 128 + uB * 16);
    bDst[1] = swz(((uint32_t)(tid >> 3) + 64) * 128 + uB * 16);

    const int aRowSub = lane & 15;
    const int aColSel = (lane >> 4) * 16;
    const int bMat    = lane >> 3;
    const int bSub    = lane & 7;
    const int bNfSel  = bMat >> 1;
    const int bKSel   = (bMat & 1) * 16;

    float acc[4][4][4];
#pragma unroll
    for (int mf = 0; mf < 4; mf++)
#pragma unroll
        for (int nf = 0; nf < 4; nf++)
#pragma unroll
            for (int i = 0; i < 4; i++) acc[mf][nf][i] = 0.f;

    if (tid == 0) {
        MBAR_EXPECT_TX(sb + MB_OFF, A_BYTES);
        BULK_G2S(sb, (const char*)g_w2t, A_BYTES, sb + MB_OFF);
    }
#pragma unroll
    for (int h = 0; h < 2; h++)
        CP16(sb + B_OFF + bDst[h], g_h1t + pixBase[h]);
    CP_COMMIT();

    for (int t = 0; t < NCHUNK; t++) {
        const int s = t & 1, s2 = s ^ 1;
        if (t + 1 < NCHUNK) {
            const int tn = t + 1;
            const int kk = tn >> 2, cq = tn & 3;
            if (tid == 0) {
                MBAR_EXPECT_TX(sb + MB_OFF + 8 * s2, A_BYTES);
                BULK_G2S(sb + s2 * STAGE_BYTES,
                         (const char*)(g_w2t + (size_t)tn * 16384),
                         A_BYTES, sb + MB_OFF + 8 * s2);
            }
            const int ky = kk / 9, kx = kk - ky * 9;
            const int tap  = (ky * 20 + kx) * 256;
            const int cOff = cq * 64;
#pragma unroll
            for (int h = 0; h < 2; h++)
                CP16(sb + s2 * STAGE_BYTES + B_OFF + bDst[h],
                     g_h1t + pixBase[h] + tap + cOff);
            CP_COMMIT();
            CP_WAIT1();
        } else {
            CP_WAIT0();
        }
        MBAR_WAIT(sb + MB_OFF + 8 * s, (t >> 1) & 1);
        __syncthreads();

        const uint32_t stb = sb + s * STAGE_BYTES;
        const uint32_t aa = stb;
        const uint32_t bb = stb + B_OFF;

#pragma unroll
        for (int q = 0; q < 4; q++) {
            const int qb = q * 32;
            uint32_t B[4][2];
#pragma unroll
            for (int gp = 0; gp < 2; gp++) {
                uint32_t off = swz((nwarp * 32 + (gp * 2 + bNfSel) * 8 + bSub) * 128
                                   + qb + bKSel);
                uint32_t r[4];
                ldsm_x4(r, bb + off);
                B[gp*2][0] = r[0]; B[gp*2][1] = r[1];
                B[gp*2+1][0] = r[2]; B[gp*2+1][1] = r[3];
            }
#pragma unroll
            for (int mf = 0; mf < 4; mf++) {
                uint32_t A[4];
                uint32_t offA = swz((mwarp * 64 + mf * 16 + aRowSub) * 128
                                    + qb + aColSel);
                ldsm_x4(A, aa + offA);
#pragma unroll
                for (int nf = 0; nf < 4; nf++)
                    mma16816h(acc[mf][nf], A, B[nf]);
            }
        }
        __syncthreads();
    }

#pragma unroll
    for (int mf = 0; mf < 4; mf++) {
        const int coB = mwarp * 64 + mf * 16 + (lane >> 2);
        const float bias0 = b2[coB];
        const float bias1 = b2[coB + 8];
#pragma unroll
        for (int nf = 0; nf < 4; nf++) {
#pragma unroll
            for (int i = 0; i < 4; i++) {
                const int co = coB + ((i >> 1) << 3);
                const int n  = n0 + nwarp * 32 + nf * 8 + ((lane & 3) << 1) + (i & 1);
                const int bi = n / 36;
                const int pp = n - bi * 36;
                g_h2[(size_t)bi * 9216 + co * 36 + pp] =
                    acc[mf][nf][i] + ((i >> 1) ? bias1 : bias0);
            }
        }
    }
}

// ---------------------------------------------------------------------------
// u_hat + fused primary squash (unchanged R15, padded Wsm)
// ---------------------------------------------------------------------------
__global__ __launch_bounds__(256) void k_uhat(const float* __restrict__ W, int b0)
{
    __shared__ float Wsm[4 * 1440];
    __shared__ float usm[64 * 32];
    const int capg = blockIdx.x * 4;
    const int img0 = b0 + blockIdx.y * 64;
    const int id   = threadIdx.x;
    {
        const float4* Wg = (const float4*)(W + (size_t)capg * 1280);
        float4* Ws4 = (float4*)Wsm;
        for (int i = id; i < 1280; i += 256) {
            const int cap = i / 320;
            const int rem = i - cap * 320;
            const int o   = rem / 32;
            const int e4  = rem - o * 32;
            Ws4[cap * 360 + o * 36 + e4] = Wg[i];
        }
        float4* us4 = (float4*)usm;
        for (int i = id; i < 512; i += 256) {
            int im = i >> 3, r = i & 7;
            us4[i] = *(const float4*)(g_h2 + (size_t)(img0 + im) * 9216
                                      + capg * 8 + r * 4);
        }
    }
    __syncthreads();
    {
        const int im  = id >> 2;
        const int cap = id & 3;
        float* up = &usm[im * 32 + cap * 8];
        float sn = 0.f;
#pragma unroll
        for (int d = 0; d < 8; d++) sn += up[d] * up[d];
        float sc = sn / ((1.f + sn) * (sqrtf(sn) + 1e-6f));
#pragma unroll
        for (int d = 0; d < 8; d++) up[d] *= sc;
    }
    __syncthreads();

    for (int it = 0; it < 40; it++) {
        int flat = it * 256 + id;
        int oe4  = flat % 40;
        int cap  = (flat / 40) & 3;
        int im   = flat / 160;
        int o    = oe4 >> 2;
        int e0   = (oe4 & 3) * 4;
        const float*  up = &usm[im * 32 + cap * 8];
        const float4* Wp = (const float4*)&Wsm[cap * 1440 + o * 144 + e0];
        float4 acc = make_float4(0.f, 0.f, 0.f, 0.f);
#pragma unroll
        for (int d = 0; d < 8; d++) {
            float  ud = up[d];
            float4 w4 = Wp[d * 4];
            acc.x = fmaf(ud, w4.x, acc.x);
            acc.y = fmaf(ud, w4.y, acc.y);
            acc.z = fmaf(ud, w4.z, acc.z);
            acc.w = fmaf(ud, w4.w, acc.w);
        }
        __half2 h0 = __floats2half2_rn(acc.x, acc.y);
        __half2 h1 = __floats2half2_rn(acc.z, acc.w);
        uint2 pk = make_uint2(*(uint32_t*)&h0, *(uint32_t*)&h1);
        *(uint2*)&g_uhat_h[((size_t)(img0 + im) * 1152 + capg + cap) * 160
                           + o * 16 + e0] = pk;
    }
}

// ---------------------------------------------------------------------------
// fused routing iteration (unchanged R15)
// ---------------------------------------------------------------------------
__global__ __launch_bounds__(160) void k_route(int uniform, int b0)
{
    __shared__ __align__(16) __half tile[128 * 168];
    __shared__ float vs[160];
    __shared__ float c_sm[128][10];
    const int b     = b0 + blockIdx.x;
    const int chunk = blockIdx.y;
    const int tid   = threadIdx.x;
    const __half* ub = g_uhat_h + (size_t)b * 184320 + (size_t)chunk * 128 * 160;

    if (uniform) {
        const int oe = tid;
        float acc = 0.f;
#pragma unroll 4
        for (int cap = 0; cap < 128; cap++)
            acc += __half2float(ub[(size_t)cap * 160 + oe]);
        g_spart[((size_t)chunk * 512 + b) * 160 + oe] = acc * 0.1f;
        return;
    }

    vs[tid] = g_vsum[b * 160 + tid];
    for (int f = tid; f < 2560; f += 160) {
        const int r = f / 20, j = f % 20;
        *(uint4*)&tile[r * 168 + j * 8] = *(const uint4*)(ub + (size_t)r * 160 + j * 8);
    }
    __syncthreads();

    if (tid < 128) {
        const __half2* row = (const __half2*)&tile[tid * 168];
        float t[10];
#pragma unroll
        for (int o = 0; o < 10; o++) {
            float s = 0.f;
#pragma unroll
            for (int e2 = 0; e2 < 8; e2++) {
                float2 f = __half22float2(row[o * 8 + e2]);
                s += f.x * vs[o * 16 + e2 * 2] + f.y * vs[o * 16 + e2 * 2 + 1];
            }
            t[o] = s;
        }
        float m = t[0];
#pragma unroll
        for (int o = 1; o < 10; o++) m = fmaxf(m, t[o]);
        float se = 0.f;
#pragma unroll
        for (int o = 0; o < 10; o++) { t[o] = expf(t[o] - m); se += t[o]; }
        float inv = 1.f / se;
#pragma unroll
        for (int o = 0; o < 10; o++) c_sm[tid][o] = t[o] * inv;
    }
    __syncthreads();

    const int oe = tid;
    const int o  = oe >> 4;
    float acc = 0.f;
#pragma unroll 4
    for (int cap = 0; cap < 128; cap++)
        acc = fmaf(c_sm[cap][o], __half2float(tile[cap * 168 + oe]), acc);
    g_spart[((size_t)chunk * 512 + b) * 160 + oe] = acc;
}

// ---------------------------------------------------------------------------
// sum partials + squash (unchanged R15)
// ---------------------------------------------------------------------------
__global__ void k_squash_v(float* __restrict__ out, int mode, int b0, int npair)
{
    int lidx = blockIdx.x * 256 + threadIdx.x;
    if (lidx >= npair) return;
    const size_t idx = (size_t)b0 * 10 + lidx;
    float4 r[4];
#pragma unroll
    for (int i = 0; i < 4; i++) r[i] = make_float4(0.f, 0.f, 0.f, 0.f);
#pragma unroll
    for (int p = 0; p < 9; p++) {
        const float4* sp = (const float4*)(g_spart + (size_t)p * 81920
                                           + idx * 16);
#pragma unroll
        for (int i = 0; i < 4; i++) {
            float4 v = sp[i];
            r[i].x += v.x; r[i].y += v.y; r[i].z += v.z; r[i].w += v.w;
        }
    }
    float sn = 0.f;
#pragma unroll
    for (int i = 0; i < 4; i++)
        sn += r[i].x*r[i].x + r[i].y*r[i].y + r[i].z*r[i].z + r[i].w*r[i].w;
    float sc = sn / ((1.f + sn) * (sqrtf(sn) + 1e-6f));
#pragma unroll
    for (int i = 0; i < 4; i++) {
        r[i].x *= sc; r[i].y *= sc; r[i].z *= sc; r[i].w *= sc;
    }
    if (mode == 0) {
        float4* q = (float4*)(g_vsum + idx * 16);
#pragma unroll
        for (int i = 0; i < 4; i++) q[i] = r[i];
    } else if (mode == 1) {
        float4* q = (float4*)(g_vsum + idx * 16);
#pragma unroll
        for (int i = 0; i < 4; i++) {
            float4 old = q[i];
            old.x += r[i].x; old.y += r[i].y; old.z += r[i].z; old.w += r[i].w;
            q[i] = old;
        }
    } else {
        float4* q = (float4*)(out + idx * 16);
#pragma unroll
        for (int i = 0; i < 4; i++) q[i] = r[i];
    }
}

// ---------------------------------------------------------------------------
extern "C" void kernel_launch(void* const* d_in, const int* in_sizes, int n_in,
                              void* d_out, int out_size)
{
    const float* x   = (const float*)d_in[0];
    const float* w1  = (const float*)d_in[1];
    const float* b1  = (const float*)d_in[2];
    const float* w2  = (const float*)d_in[3];
    const float* b2  = (const float*)d_in[4];
    const float* W   = (const float*)d_in[5];
    float* out = (float*)d_out;

    cudaFuncSetAttribute(k_conv1mma,
                         cudaFuncAttributeMaxDynamicSharedMemorySize, C1_SMEM);
    cudaFuncSetAttribute(k_conv2mma,
                         cudaFuncAttributeMaxDynamicSharedMemorySize, 98336);

    k_w1prep<<<256, 256>>>(w1);
    k_wprep<<<dim3(256, 2), 256>>>(w2);
    k_conv1mma<<<3200, 512, C1_SMEM>>>(x, b1);
    k_conv2mma<<<144, 512, 98336>>>(b2);

    for (int c = 0; c < 4; c++) {
        const int b0 = c * 128;
        k_uhat<<<dim3(288, 2), 256>>>(W, b0);
        k_route<<<dim3(128, 9), 160>>>(1, b0);
        k_squash_v<<<5, 256>>>(nullptr, 0, b0, 1280);
        k_route<<<dim3(128, 9), 160>>>(0, b0);
        k_squash_v<<<5, 256>>>(nullptr, 1, b0, 1280);
        k_route<<<dim3(128, 9), 160>>>(0, b0);
        k_squash_v<<<5, 256>>>(out, 2, b0, 1280);
    }
}